// round 1
// baseline (speedup 1.0000x reference)
#include <cuda_runtime.h>

#define T_TOK 8192
#define DM    1024
#define NE    8
#define CAP   1024
#define DFF   4096

// ---------------- scratch (static device globals; no runtime allocation) ----------------
__device__ float g_gate[T_TOK];
__device__ int   g_expert[T_TOK];
__device__ int   g_bcnt[NE];
__device__ int   g_btok[NE][T_TOK];
__device__ float g_bgate[NE][T_TOK];
__device__ int   g_scnt[NE];
__device__ int   g_stok[NE][CAP];
__device__ float g_sgate[NE][CAP];
__device__ float g_psum[NE];
__device__ int   g_cnt[NE];
__device__ float g_H[(size_t)NE * CAP * DFF];   // 128 MiB intermediate H = relu(XW1+b1)

// ---------------- init: zero the small counters each replay ----------------
__global__ void init_kernel() {
    int i = threadIdx.x;
    if (i < NE) { g_bcnt[i] = 0; g_scnt[i] = 0; g_psum[i] = 0.f; g_cnt[i] = 0; }
}

// ---------------- router: one warp per token ----------------
__global__ void router_kernel(const float* __restrict__ x, const float* __restrict__ Wr) {
    __shared__ float s_ps[NE];
    __shared__ int   s_cnt[NE];
    int tid = threadIdx.x;
    if (tid < NE) { s_ps[tid] = 0.f; s_cnt[tid] = 0; }
    __syncthreads();

    int warp = tid >> 5, lane = tid & 31;
    int t = blockIdx.x * 8 + warp;
    const float* xr = x + (size_t)t * DM;

    float acc[NE];
#pragma unroll
    for (int e = 0; e < NE; e++) acc[e] = 0.f;

#pragma unroll 8
    for (int k = 0; k < 32; k++) {
        int d = lane + 32 * k;
        float xv = xr[d];
        float4 w0 = *(const float4*)(Wr + (size_t)d * 8);
        float4 w1 = *(const float4*)(Wr + (size_t)d * 8 + 4);
        acc[0] += xv * w0.x; acc[1] += xv * w0.y; acc[2] += xv * w0.z; acc[3] += xv * w0.w;
        acc[4] += xv * w1.x; acc[5] += xv * w1.y; acc[6] += xv * w1.z; acc[7] += xv * w1.w;
    }
#pragma unroll
    for (int off = 16; off > 0; off >>= 1)
#pragma unroll
        for (int e = 0; e < NE; e++)
            acc[e] += __shfl_down_sync(0xffffffffu, acc[e], off);

    if (lane == 0) {
        float m = acc[0]; int ai = 0;
#pragma unroll
        for (int e = 1; e < NE; e++) if (acc[e] > m) { m = acc[e]; ai = e; }
        float p[NE], s = 0.f;
#pragma unroll
        for (int e = 0; e < NE; e++) { p[e] = expf(acc[e] - m); s += p[e]; }
        float inv = 1.f / s;
        g_gate[t]   = p[ai] * inv;
        g_expert[t] = ai;
#pragma unroll
        for (int e = 0; e < NE; e++) atomicAdd(&s_ps[e], p[e] * inv);
        atomicAdd(&s_cnt[ai], 1);
    }
    __syncthreads();
    if (tid < NE) {
        atomicAdd(&g_psum[tid], s_ps[tid]);
        atomicAdd(&g_cnt[tid],  s_cnt[tid]);
    }
}

// ---------------- bucketize tokens per expert (warp-aggregated atomics) ----------------
__global__ void bucketize_kernel() {
    int t = blockIdx.x * blockDim.x + threadIdx.x;
    if (t >= T_TOK) return;
    int e = g_expert[t];
    int lane = threadIdx.x & 31;
    unsigned mask = __match_any_sync(0xffffffffu, e);
    int leader = __ffs(mask) - 1;
    int rank   = __popc(mask & ((1u << lane) - 1));
    int base = 0;
    if (lane == leader) base = atomicAdd(&g_bcnt[e], __popc(mask));
    base = __shfl_sync(0xffffffffu, base, leader);
    int pos = base + rank;
    g_btok[e][pos]  = t;
    g_bgate[e][pos] = g_gate[t];
}

// ---------------- exact capacity selection (matches jax.lax.top_k tie-break) ----------------
__global__ void select_kernel() {
    int t = blockIdx.x * blockDim.x + threadIdx.x;
    if (t >= T_TOK) return;
    int e = g_expert[t];
    float g = g_gate[t];
    int n = g_bcnt[e];
    int rank = 0;
    for (int j = 0; j < n; j++) {
        float gj = g_bgate[e][j];
        if (gj > g) rank++;
        else if (gj == g && g_btok[e][j] < t) rank++;  // lower index wins ties
    }
    if (rank < CAP) {
        int pos = atomicAdd(&g_scnt[e], 1);
        g_stok[e][pos]  = t;
        g_sgate[e][pos] = g;
    }
}

// ---------------- FFN GEMM 1: H = relu(X_gathered @ W1[e] + b1[e]) ----------------
// 128x128 tile, K-tile 16, 256 threads, 8x8 microtile (split as 2x float4 column groups)
__global__ __launch_bounds__(256) void ffn1_kernel(const float* __restrict__ x,
                                                   const float* __restrict__ W1,
                                                   const float* __restrict__ bias1) {
    int e = blockIdx.z;
    int M = g_scnt[e];
    int m0 = blockIdx.y * 128;
    if (m0 >= M) return;
    int n0 = blockIdx.x * 128;

    __shared__ float As[128][17];
    __shared__ float Bs[16][132];

    int tid = threadIdx.x;
    int tx = tid & 15, ty = tid >> 4;
    int am = tid >> 1, ak = (tid & 1) * 8;
    int gm = m0 + am;
    const float* arow = (gm < M) ? (x + (size_t)g_stok[e][gm] * DM) : 0;
    int bk = tid >> 4, bn = (tid & 15) * 8;
    const float* Bbase = W1 + (size_t)e * DM * DFF + n0;

    float acc[8][8];
#pragma unroll
    for (int i = 0; i < 8; i++)
#pragma unroll
        for (int j = 0; j < 8; j++) acc[i][j] = 0.f;

    for (int k0 = 0; k0 < DM; k0 += 16) {
        if (arow) {
            float4 v0 = *(const float4*)(arow + k0 + ak);
            float4 v1 = *(const float4*)(arow + k0 + ak + 4);
            As[am][ak + 0] = v0.x; As[am][ak + 1] = v0.y; As[am][ak + 2] = v0.z; As[am][ak + 3] = v0.w;
            As[am][ak + 4] = v1.x; As[am][ak + 5] = v1.y; As[am][ak + 6] = v1.z; As[am][ak + 7] = v1.w;
        } else {
#pragma unroll
            for (int i = 0; i < 8; i++) As[am][ak + i] = 0.f;
        }
        const float* bp = Bbase + (size_t)(k0 + bk) * DFF + bn;
        *(float4*)&Bs[bk][bn]     = *(const float4*)bp;
        *(float4*)&Bs[bk][bn + 4] = *(const float4*)(bp + 4);
        __syncthreads();

#pragma unroll
        for (int kk = 0; kk < 16; kk++) {
            float a[8];
#pragma unroll
            for (int i = 0; i < 8; i++) a[i] = As[ty * 8 + i][kk];
            float4 b0 = *(const float4*)&Bs[kk][tx * 4];
            float4 b1 = *(const float4*)&Bs[kk][64 + tx * 4];
            float b[8] = {b0.x, b0.y, b0.z, b0.w, b1.x, b1.y, b1.z, b1.w};
#pragma unroll
            for (int i = 0; i < 8; i++)
#pragma unroll
                for (int j = 0; j < 8; j++) acc[i][j] += a[i] * b[j];
        }
        __syncthreads();
    }

    float4 c0 = *(const float4*)(bias1 + (size_t)e * DFF + n0 + tx * 4);
    float4 c1 = *(const float4*)(bias1 + (size_t)e * DFF + n0 + 64 + tx * 4);
    float bb[8] = {c0.x, c0.y, c0.z, c0.w, c1.x, c1.y, c1.z, c1.w};

#pragma unroll
    for (int i = 0; i < 8; i++) {
        int m = m0 + ty * 8 + i;
        if (m < M) {
            float* hp = g_H + ((size_t)e * CAP + m) * DFF + n0;
            float4 o0, o1;
            o0.x = fmaxf(acc[i][0] + bb[0], 0.f); o0.y = fmaxf(acc[i][1] + bb[1], 0.f);
            o0.z = fmaxf(acc[i][2] + bb[2], 0.f); o0.w = fmaxf(acc[i][3] + bb[3], 0.f);
            o1.x = fmaxf(acc[i][4] + bb[4], 0.f); o1.y = fmaxf(acc[i][5] + bb[5], 0.f);
            o1.z = fmaxf(acc[i][6] + bb[6], 0.f); o1.w = fmaxf(acc[i][7] + bb[7], 0.f);
            *(float4*)(hp + tx * 4)      = o0;
            *(float4*)(hp + 64 + tx * 4) = o1;
        }
    }
}

// ---------------- FFN GEMM 2: out[t] = gate * (H @ W2[e] + b2[e]) ----------------
__global__ __launch_bounds__(256) void ffn2_kernel(const float* __restrict__ W2,
                                                   const float* __restrict__ bias2,
                                                   float* __restrict__ out) {
    int e = blockIdx.z;
    int M = g_scnt[e];
    int m0 = blockIdx.y * 128;
    if (m0 >= M) return;
    int n0 = blockIdx.x * 128;

    __shared__ float As[128][17];
    __shared__ float Bs[16][132];

    int tid = threadIdx.x;
    int tx = tid & 15, ty = tid >> 4;
    int am = tid >> 1, ak = (tid & 1) * 8;
    int gm = m0 + am;
    const float* arow = (gm < M) ? (g_H + ((size_t)e * CAP + gm) * DFF) : 0;
    int bk = tid >> 4, bn = (tid & 15) * 8;
    const float* Bbase = W2 + (size_t)e * DFF * DM + n0;

    float acc[8][8];
#pragma unroll
    for (int i = 0; i < 8; i++)
#pragma unroll
        for (int j = 0; j < 8; j++) acc[i][j] = 0.f;

    for (int k0 = 0; k0 < DFF; k0 += 16) {
        if (arow) {
            float4 v0 = *(const float4*)(arow + k0 + ak);
            float4 v1 = *(const float4*)(arow + k0 + ak + 4);
            As[am][ak + 0] = v0.x; As[am][ak + 1] = v0.y; As[am][ak + 2] = v0.z; As[am][ak + 3] = v0.w;
            As[am][ak + 4] = v1.x; As[am][ak + 5] = v1.y; As[am][ak + 6] = v1.z; As[am][ak + 7] = v1.w;
        } else {
#pragma unroll
            for (int i = 0; i < 8; i++) As[am][ak + i] = 0.f;
        }
        const float* bp = Bbase + (size_t)(k0 + bk) * DM + bn;
        *(float4*)&Bs[bk][bn]     = *(const float4*)bp;
        *(float4*)&Bs[bk][bn + 4] = *(const float4*)(bp + 4);
        __syncthreads();

#pragma unroll
        for (int kk = 0; kk < 16; kk++) {
            float a[8];
#pragma unroll
            for (int i = 0; i < 8; i++) a[i] = As[ty * 8 + i][kk];
            float4 b0 = *(const float4*)&Bs[kk][tx * 4];
            float4 b1 = *(const float4*)&Bs[kk][64 + tx * 4];
            float b[8] = {b0.x, b0.y, b0.z, b0.w, b1.x, b1.y, b1.z, b1.w};
#pragma unroll
            for (int i = 0; i < 8; i++)
#pragma unroll
                for (int j = 0; j < 8; j++) acc[i][j] += a[i] * b[j];
        }
        __syncthreads();
    }

    float4 c0 = *(const float4*)(bias2 + (size_t)e * DM + n0 + tx * 4);
    float4 c1 = *(const float4*)(bias2 + (size_t)e * DM + n0 + 64 + tx * 4);
    float bb[8] = {c0.x, c0.y, c0.z, c0.w, c1.x, c1.y, c1.z, c1.w};

#pragma unroll
    for (int i = 0; i < 8; i++) {
        int m = m0 + ty * 8 + i;
        if (m < M) {
            int t = g_stok[e][m];
            float gt = g_sgate[e][m];
            float* op = out + (size_t)t * DM + n0;
            float4 o0, o1;
            o0.x = gt * (acc[i][0] + bb[0]); o0.y = gt * (acc[i][1] + bb[1]);
            o0.z = gt * (acc[i][2] + bb[2]); o0.w = gt * (acc[i][3] + bb[3]);
            o1.x = gt * (acc[i][4] + bb[4]); o1.y = gt * (acc[i][5] + bb[5]);
            o1.z = gt * (acc[i][6] + bb[6]); o1.w = gt * (acc[i][7] + bb[7]);
            *(float4*)(op + tx * 4)      = o0;
            *(float4*)(op + 64 + tx * 4) = o1;
        }
    }
}

// ---------------- load-balancing loss (appended scalar, if present) ----------------
__global__ void loss_kernel(float* __restrict__ out, int out_size) {
    if (out_size > T_TOK * DM) {
        float loss = 0.f;
#pragma unroll
        for (int e = 0; e < NE; e++)
            loss += ((float)g_cnt[e] / (float)T_TOK) * (g_psum[e] / (float)T_TOK);
        out[T_TOK * DM] = (float)NE * loss;
    }
}

// ---------------- launch ----------------
extern "C" void kernel_launch(void* const* d_in, const int* in_sizes, int n_in,
                              void* d_out, int out_size) {
    const float* x   = (const float*)d_in[0];
    const float* Wr  = (const float*)d_in[1];
    const float* W1  = (const float*)d_in[2];
    const float* b1  = (const float*)d_in[3];
    const float* W2  = (const float*)d_in[4];
    const float* b2  = (const float*)d_in[5];
    float* out = (float*)d_out;

    cudaMemsetAsync(d_out, 0, (size_t)out_size * sizeof(float));
    init_kernel<<<1, 32>>>();
    router_kernel<<<T_TOK / 8, 256>>>(x, Wr);
    bucketize_kernel<<<T_TOK / 256, 256>>>();
    select_kernel<<<T_TOK / 256, 256>>>();
    dim3 g1(DFF / 128, CAP / 128, NE);
    ffn1_kernel<<<g1, 256>>>(x, W1, b1);
    dim3 g2(DM / 128, CAP / 128, NE);
    ffn2_kernel<<<g2, 256>>>(W2, b2, out);
    loss_kernel<<<1, 1>>>(out, out_size);
}

// round 2
// speedup vs baseline: 1.8944x; 1.8944x over previous
#include <cuda_runtime.h>

#define T_TOK 8192
#define DM    1024
#define NE    8
#define CAP   1024
#define DFF   4096

// ---------------- scratch ----------------
__device__ float g_gate[T_TOK];
__device__ int   g_expert[T_TOK];
__device__ int   g_bcnt[NE];
__device__ int   g_btok[NE][T_TOK];
__device__ float g_bgate[NE][T_TOK];
__device__ int   g_scnt[NE];
__device__ int   g_stok[NE][CAP];
__device__ float g_sgate[NE][CAP];
__device__ float g_psum[NE];
__device__ int   g_cnt[NE];
__device__ float g_H[(size_t)NE * CAP * DFF];   // fp32 intermediate H

// ---------------- helpers ----------------
__device__ __forceinline__ unsigned f2tf(float f) {
    unsigned u; asm("cvt.rna.tf32.f32 %0, %1;" : "=r"(u) : "f"(f)); return u;
}
__device__ __forceinline__ void mma_tf32(float* c, const unsigned* a, const unsigned* b) {
    asm volatile(
        "mma.sync.aligned.m16n8k8.row.col.f32.tf32.tf32.f32 "
        "{%0,%1,%2,%3},{%4,%5,%6,%7},{%8,%9},{%0,%1,%2,%3};"
        : "+f"(c[0]), "+f"(c[1]), "+f"(c[2]), "+f"(c[3])
        : "r"(a[0]), "r"(a[1]), "r"(a[2]), "r"(a[3]), "r"(b[0]), "r"(b[1]));
}

// ---------------- init ----------------
__global__ void init_kernel() {
    int i = threadIdx.x;
    if (i < NE) { g_bcnt[i] = 0; g_scnt[i] = 0; g_psum[i] = 0.f; g_cnt[i] = 0; }
}

// ---------------- router: one warp per token ----------------
__global__ void router_kernel(const float* __restrict__ x, const float* __restrict__ Wr) {
    __shared__ float s_ps[NE];
    __shared__ int   s_cnt[NE];
    int tid = threadIdx.x;
    if (tid < NE) { s_ps[tid] = 0.f; s_cnt[tid] = 0; }
    __syncthreads();

    int warp = tid >> 5, lane = tid & 31;
    int t = blockIdx.x * 8 + warp;
    const float* xr = x + (size_t)t * DM;

    float acc[NE];
#pragma unroll
    for (int e = 0; e < NE; e++) acc[e] = 0.f;

#pragma unroll 8
    for (int k = 0; k < 32; k++) {
        int d = lane + 32 * k;
        float xv = xr[d];
        float4 w0 = *(const float4*)(Wr + (size_t)d * 8);
        float4 w1 = *(const float4*)(Wr + (size_t)d * 8 + 4);
        acc[0] += xv * w0.x; acc[1] += xv * w0.y; acc[2] += xv * w0.z; acc[3] += xv * w0.w;
        acc[4] += xv * w1.x; acc[5] += xv * w1.y; acc[6] += xv * w1.z; acc[7] += xv * w1.w;
    }
#pragma unroll
    for (int off = 16; off > 0; off >>= 1)
#pragma unroll
        for (int e = 0; e < NE; e++)
            acc[e] += __shfl_down_sync(0xffffffffu, acc[e], off);

    if (lane == 0) {
        float m = acc[0]; int ai = 0;
#pragma unroll
        for (int e = 1; e < NE; e++) if (acc[e] > m) { m = acc[e]; ai = e; }
        float p[NE], s = 0.f;
#pragma unroll
        for (int e = 0; e < NE; e++) { p[e] = expf(acc[e] - m); s += p[e]; }
        float inv = 1.f / s;
        g_gate[t]   = p[ai] * inv;
        g_expert[t] = ai;
#pragma unroll
        for (int e = 0; e < NE; e++) atomicAdd(&s_ps[e], p[e] * inv);
        atomicAdd(&s_cnt[ai], 1);
    }
    __syncthreads();
    if (tid < NE) {
        atomicAdd(&g_psum[tid], s_ps[tid]);
        atomicAdd(&g_cnt[tid],  s_cnt[tid]);
    }
}

// ---------------- bucketize (warp-aggregated atomics) ----------------
__global__ void bucketize_kernel() {
    int t = blockIdx.x * blockDim.x + threadIdx.x;
    if (t >= T_TOK) return;
    int e = g_expert[t];
    int lane = threadIdx.x & 31;
    unsigned mask = __match_any_sync(0xffffffffu, e);
    int leader = __ffs(mask) - 1;
    int rank   = __popc(mask & ((1u << lane) - 1));
    int base = 0;
    if (lane == leader) base = atomicAdd(&g_bcnt[e], __popc(mask));
    base = __shfl_sync(0xffffffffu, base, leader);
    int pos = base + rank;
    g_btok[e][pos]  = t;
    g_bgate[e][pos] = g_gate[t];
}

// ---------------- capacity selection: block per expert, smem-chunked scan ----------------
#define SEL_TPB 512
#define SEL_CHUNK 2048
__global__ __launch_bounds__(SEL_TPB) void select_kernel() {
    int e = blockIdx.x;
    int n = g_bcnt[e];
    __shared__ float sg[SEL_CHUNK];
    __shared__ int   stk[SEL_CHUNK];

    for (int i0 = 0; i0 < n; i0 += SEL_TPB) {
        int i = i0 + threadIdx.x;
        bool active = (i < n);
        float g = 0.f; int t = 0; int rank = 0;
        if (active) { g = g_bgate[e][i]; t = g_btok[e][i]; }

        for (int c0 = 0; c0 < n; c0 += SEL_CHUNK) {
            int cn = min(SEL_CHUNK, n - c0);
            __syncthreads();
            for (int j = threadIdx.x; j < cn; j += SEL_TPB) {
                sg[j]  = g_bgate[e][c0 + j];
                stk[j] = g_btok[e][c0 + j];
            }
            __syncthreads();
            if (active) {
                for (int j = 0; j < cn; j++) {
                    float gj = sg[j];
                    if (gj > g || (gj == g && stk[j] < t)) rank++;
                }
            }
        }
        if (active && rank < CAP) {
            int pos = atomicAdd(&g_scnt[e], 1);
            g_stok[e][pos]  = t;
            g_sgate[e][pos] = g;
        }
        __syncthreads();
    }
}

// ---------------- FFN GEMM 1 (tf32 tensor cores): H = relu(X_g @ W1[e] + b1[e]) ----------------
// block tile 128x128, BK=16, 256 threads = 8 warps (4 m-warps x 2 n-warps), warp tile 32x64.
__global__ __launch_bounds__(256) void ffn1_kernel(const float* __restrict__ x,
                                                   const float* __restrict__ W1,
                                                   const float* __restrict__ bias1) {
    int e = blockIdx.z;
    int M = g_scnt[e];
    int m0 = blockIdx.y * 128;
    if (m0 >= M) return;
    int n0 = blockIdx.x * 128;

    __shared__ unsigned As[128][17];   // tf32 bits, [m][k]
    __shared__ unsigned Bs[16][132];   // tf32 bits, [k][n]

    int tid = threadIdx.x;
    int wid = tid >> 5, lane = tid & 31;
    int gid = lane >> 2, tig = lane & 3;
    int m_base = (wid & 3) * 32;
    int n_base = (wid >> 2) * 64;

    int am = tid >> 1, ak = (tid & 1) * 8;
    int gm = m0 + am;
    const float* arow = (gm < M) ? (x + (size_t)g_stok[e][gm] * DM) : 0;
    int bk = tid >> 4, bn = (tid & 15) * 8;
    const float* Bbase = W1 + (size_t)e * DM * DFF + n0;

    float acc[2][8][4];
#pragma unroll
    for (int i = 0; i < 2; i++)
#pragma unroll
        for (int j = 0; j < 8; j++)
#pragma unroll
            for (int q = 0; q < 4; q++) acc[i][j][q] = 0.f;

    for (int k0 = 0; k0 < DM; k0 += 16) {
        if (arow) {
            float4 v0 = *(const float4*)(arow + k0 + ak);
            float4 v1 = *(const float4*)(arow + k0 + ak + 4);
            As[am][ak + 0] = f2tf(v0.x); As[am][ak + 1] = f2tf(v0.y);
            As[am][ak + 2] = f2tf(v0.z); As[am][ak + 3] = f2tf(v0.w);
            As[am][ak + 4] = f2tf(v1.x); As[am][ak + 5] = f2tf(v1.y);
            As[am][ak + 6] = f2tf(v1.z); As[am][ak + 7] = f2tf(v1.w);
        } else {
#pragma unroll
            for (int i = 0; i < 8; i++) As[am][ak + i] = 0u;
        }
        const float* bp = Bbase + (size_t)(k0 + bk) * DFF + bn;
        float4 w0 = *(const float4*)bp;
        float4 w1 = *(const float4*)(bp + 4);
        Bs[bk][bn + 0] = f2tf(w0.x); Bs[bk][bn + 1] = f2tf(w0.y);
        Bs[bk][bn + 2] = f2tf(w0.z); Bs[bk][bn + 3] = f2tf(w0.w);
        Bs[bk][bn + 4] = f2tf(w1.x); Bs[bk][bn + 5] = f2tf(w1.y);
        Bs[bk][bn + 6] = f2tf(w1.z); Bs[bk][bn + 7] = f2tf(w1.w);
        __syncthreads();

#pragma unroll
        for (int kk = 0; kk < 16; kk += 8) {
            unsigned a[2][4];
#pragma unroll
            for (int i = 0; i < 2; i++) {
                int r = m_base + i * 16 + gid;
                a[i][0] = As[r][kk + tig];
                a[i][1] = As[r + 8][kk + tig];
                a[i][2] = As[r][kk + tig + 4];
                a[i][3] = As[r + 8][kk + tig + 4];
            }
            unsigned b[8][2];
#pragma unroll
            for (int j = 0; j < 8; j++) {
                int c = n_base + j * 8 + gid;
                b[j][0] = Bs[kk + tig][c];
                b[j][1] = Bs[kk + tig + 4][c];
            }
#pragma unroll
            for (int i = 0; i < 2; i++)
#pragma unroll
                for (int j = 0; j < 8; j++)
                    mma_tf32(acc[i][j], a[i], b[j]);
        }
        __syncthreads();
    }

    // epilogue: relu(acc + b1) -> H
    const float* b1p = bias1 + (size_t)e * DFF + n0;
#pragma unroll
    for (int i = 0; i < 2; i++) {
        int m_lo = m0 + m_base + i * 16 + gid;
        int m_hi = m_lo + 8;
#pragma unroll
        for (int j = 0; j < 8; j++) {
            int nc = n_base + j * 8 + 2 * tig;
            float bv0 = b1p[nc], bv1 = b1p[nc + 1];
            if (m_lo < M) {
                float2 o;
                o.x = fmaxf(acc[i][j][0] + bv0, 0.f);
                o.y = fmaxf(acc[i][j][1] + bv1, 0.f);
                *(float2*)(g_H + ((size_t)e * CAP + m_lo) * DFF + n0 + nc) = o;
            }
            if (m_hi < M) {
                float2 o;
                o.x = fmaxf(acc[i][j][2] + bv0, 0.f);
                o.y = fmaxf(acc[i][j][3] + bv1, 0.f);
                *(float2*)(g_H + ((size_t)e * CAP + m_hi) * DFF + n0 + nc) = o;
            }
        }
    }
}

// ---------------- FFN GEMM 2 (tf32 tensor cores): out[t] = gate * (H @ W2[e] + b2[e]) ----------------
__global__ __launch_bounds__(256) void ffn2_kernel(const float* __restrict__ W2,
                                                   const float* __restrict__ bias2,
                                                   float* __restrict__ out) {
    int e = blockIdx.z;
    int M = g_scnt[e];
    int m0 = blockIdx.y * 128;
    if (m0 >= M) return;
    int n0 = blockIdx.x * 128;

    __shared__ unsigned As[128][17];
    __shared__ unsigned Bs[16][132];

    int tid = threadIdx.x;
    int wid = tid >> 5, lane = tid & 31;
    int gid = lane >> 2, tig = lane & 3;
    int m_base = (wid & 3) * 32;
    int n_base = (wid >> 2) * 64;

    int am = tid >> 1, ak = (tid & 1) * 8;
    int gm = m0 + am;
    const float* arow = (gm < M) ? (g_H + ((size_t)e * CAP + gm) * DFF) : 0;
    int bk = tid >> 4, bn = (tid & 15) * 8;
    const float* Bbase = W2 + (size_t)e * DFF * DM + n0;

    float acc[2][8][4];
#pragma unroll
    for (int i = 0; i < 2; i++)
#pragma unroll
        for (int j = 0; j < 8; j++)
#pragma unroll
            for (int q = 0; q < 4; q++) acc[i][j][q] = 0.f;

    for (int k0 = 0; k0 < DFF; k0 += 16) {
        if (arow) {
            float4 v0 = *(const float4*)(arow + k0 + ak);
            float4 v1 = *(const float4*)(arow + k0 + ak + 4);
            As[am][ak + 0] = f2tf(v0.x); As[am][ak + 1] = f2tf(v0.y);
            As[am][ak + 2] = f2tf(v0.z); As[am][ak + 3] = f2tf(v0.w);
            As[am][ak + 4] = f2tf(v1.x); As[am][ak + 5] = f2tf(v1.y);
            As[am][ak + 6] = f2tf(v1.z); As[am][ak + 7] = f2tf(v1.w);
        } else {
#pragma unroll
            for (int i = 0; i < 8; i++) As[am][ak + i] = 0u;
        }
        const float* bp = Bbase + (size_t)(k0 + bk) * DM + bn;
        float4 w0 = *(const float4*)bp;
        float4 w1 = *(const float4*)(bp + 4);
        Bs[bk][bn + 0] = f2tf(w0.x); Bs[bk][bn + 1] = f2tf(w0.y);
        Bs[bk][bn + 2] = f2tf(w0.z); Bs[bk][bn + 3] = f2tf(w0.w);
        Bs[bk][bn + 4] = f2tf(w1.x); Bs[bk][bn + 5] = f2tf(w1.y);
        Bs[bk][bn + 6] = f2tf(w1.z); Bs[bk][bn + 7] = f2tf(w1.w);
        __syncthreads();

#pragma unroll
        for (int kk = 0; kk < 16; kk += 8) {
            unsigned a[2][4];
#pragma unroll
            for (int i = 0; i < 2; i++) {
                int r = m_base + i * 16 + gid;
                a[i][0] = As[r][kk + tig];
                a[i][1] = As[r + 8][kk + tig];
                a[i][2] = As[r][kk + tig + 4];
                a[i][3] = As[r + 8][kk + tig + 4];
            }
            unsigned b[8][2];
#pragma unroll
            for (int j = 0; j < 8; j++) {
                int c = n_base + j * 8 + gid;
                b[j][0] = Bs[kk + tig][c];
                b[j][1] = Bs[kk + tig + 4][c];
            }
#pragma unroll
            for (int i = 0; i < 2; i++)
#pragma unroll
                for (int j = 0; j < 8; j++)
                    mma_tf32(acc[i][j], a[i], b[j]);
        }
        __syncthreads();
    }

    const float* b2p = bias2 + (size_t)e * DM + n0;
#pragma unroll
    for (int i = 0; i < 2; i++) {
        int m_lo = m0 + m_base + i * 16 + gid;
        int m_hi = m_lo + 8;
#pragma unroll
        for (int j = 0; j < 8; j++) {
            int nc = n_base + j * 8 + 2 * tig;
            float bv0 = b2p[nc], bv1 = b2p[nc + 1];
            if (m_lo < M) {
                int t = g_stok[e][m_lo];
                float gt = g_sgate[e][m_lo];
                float2 o;
                o.x = gt * (acc[i][j][0] + bv0);
                o.y = gt * (acc[i][j][1] + bv1);
                *(float2*)(out + (size_t)t * DM + n0 + nc) = o;
            }
            if (m_hi < M) {
                int t = g_stok[e][m_hi];
                float gt = g_sgate[e][m_hi];
                float2 o;
                o.x = gt * (acc[i][j][2] + bv0);
                o.y = gt * (acc[i][j][3] + bv1);
                *(float2*)(out + (size_t)t * DM + n0 + nc) = o;
            }
        }
    }
}

// ---------------- load-balancing loss ----------------
__global__ void loss_kernel(float* __restrict__ out, int out_size) {
    if (out_size > T_TOK * DM) {
        float loss = 0.f;
#pragma unroll
        for (int e = 0; e < NE; e++)
            loss += ((float)g_cnt[e] / (float)T_TOK) * (g_psum[e] / (float)T_TOK);
        out[T_TOK * DM] = (float)NE * loss;
    }
}

// ---------------- launch ----------------
extern "C" void kernel_launch(void* const* d_in, const int* in_sizes, int n_in,
                              void* d_out, int out_size) {
    const float* x   = (const float*)d_in[0];
    const float* Wr  = (const float*)d_in[1];
    const float* W1  = (const float*)d_in[2];
    const float* b1  = (const float*)d_in[3];
    const float* W2  = (const float*)d_in[4];
    const float* b2  = (const float*)d_in[5];
    float* out = (float*)d_out;

    cudaMemsetAsync(d_out, 0, (size_t)out_size * sizeof(float));
    init_kernel<<<1, 32>>>();
    router_kernel<<<T_TOK / 8, 256>>>(x, Wr);
    bucketize_kernel<<<T_TOK / 256, 256>>>();
    select_kernel<<<NE, SEL_TPB>>>();
    dim3 g1(DFF / 128, CAP / 128, NE);
    ffn1_kernel<<<g1, 256>>>(x, W1, b1);
    dim3 g2(DM / 128, CAP / 128, NE);
    ffn2_kernel<<<g2, 256>>>(W2, b2, out);
    loss_kernel<<<1, 1>>>(out, out_size);
}

// round 4
// speedup vs baseline: 3.6124x; 1.9070x over previous
#include <cuda_runtime.h>
#include <cstdint>

#define T_TOK 8192
#define DM    1024
#define NE    8
#define CAP   1024
#define DFF   4096

#define BM 128
#define BN 256
#define BK 32

#define APITCH 36           // floats per A smem row (pad 4)
#define BPITCH 264          // floats per B smem row (pad 8)
#define A_F (BM * APITCH)   // 4608 floats
#define B_F (BK * BPITCH)   // 8448 floats
#define STAGE_F (A_F + B_F) // 13056 floats
#define SMEM_BYTES (2 * STAGE_F * 4)  // 104448 bytes

// ---------------- scratch ----------------
__device__ float g_gate[T_TOK];
__device__ int   g_expert[T_TOK];
__device__ int   g_bcnt[NE];
__device__ int   g_btok[NE][T_TOK];
__device__ float g_bgate[NE][T_TOK];
__device__ int   g_scnt[NE];
__device__ int   g_stok[NE][CAP];
__device__ float g_sgate[NE][CAP];
__device__ float g_psum[NE];
__device__ int   g_cnt[NE];
__device__ float g_Xtf[(size_t)T_TOK * DM];        // x pre-rounded to tf32
__device__ float g_W1tf[(size_t)NE * DM * DFF];    // W1 rounded to tf32, layout unchanged [e][k][n]
__device__ float g_W2tf[(size_t)NE * DFF * DM];    // W2 rounded to tf32, [e][k][n]
__device__ float g_H[(size_t)NE * CAP * DFF];      // H, tf32-rounded

// ---------------- helpers ----------------
__device__ __forceinline__ unsigned f2tf(float f) {
    unsigned u; asm("cvt.rna.tf32.f32 %0, %1;" : "=r"(u) : "f"(f)); return u;
}
__device__ __forceinline__ uint32_t smem_u32(const void* p) {
    uint32_t a; asm("{ .reg .u64 t; cvta.to.shared.u64 t, %1; cvt.u32.u64 %0, t; }" : "=r"(a) : "l"(p));
    return a;
}
__device__ __forceinline__ void cp16(uint32_t dst, const void* src) {
    asm volatile("cp.async.cg.shared.global [%0], [%1], 16;" :: "r"(dst), "l"(src));
}
__device__ __forceinline__ void cp_commit() { asm volatile("cp.async.commit_group;"); }
template<int N> __device__ __forceinline__ void cp_wait() {
    asm volatile("cp.async.wait_group %0;" :: "n"(N));
}
__device__ __forceinline__ void mma_tf32(float* c, const unsigned* a, const unsigned* b) {
    asm volatile(
        "mma.sync.aligned.m16n8k8.row.col.f32.tf32.tf32.f32 "
        "{%0,%1,%2,%3},{%4,%5,%6,%7},{%8,%9},{%0,%1,%2,%3};"
        : "+f"(c[0]), "+f"(c[1]), "+f"(c[2]), "+f"(c[3])
        : "r"(a[0]), "r"(a[1]), "r"(a[2]), "r"(a[3]), "r"(b[0]), "r"(b[1]));
}

// ---------------- init ----------------
__global__ void init_kernel() {
    int i = threadIdx.x;
    if (i < NE) { g_bcnt[i] = 0; g_scnt[i] = 0; g_psum[i] = 0.f; g_cnt[i] = 0; }
}

// ---------------- elementwise tf32 pre-round (float4 per thread) ----------------
__global__ void roundtf_kernel(const float4* __restrict__ src, float4* __restrict__ dst) {
    size_t i = (size_t)blockIdx.x * blockDim.x + threadIdx.x;
    float4 v = src[i];
    v.x = __uint_as_float(f2tf(v.x));
    v.y = __uint_as_float(f2tf(v.y));
    v.z = __uint_as_float(f2tf(v.z));
    v.w = __uint_as_float(f2tf(v.w));
    dst[i] = v;
}

// ---------------- router: one warp per token; writes tf32-rounded x ----------------
__global__ void router_kernel(const float* __restrict__ x, const float* __restrict__ Wr) {
    __shared__ float s_ps[NE];
    __shared__ int   s_cnt[NE];
    int tid = threadIdx.x;
    if (tid < NE) { s_ps[tid] = 0.f; s_cnt[tid] = 0; }
    __syncthreads();

    int warp = tid >> 5, lane = tid & 31;
    int t = blockIdx.x * 8 + warp;
    const float* xr = x + (size_t)t * DM;
    float* xo = g_Xtf + (size_t)t * DM;

    float acc[NE];
#pragma unroll
    for (int e = 0; e < NE; e++) acc[e] = 0.f;

#pragma unroll 8
    for (int k = 0; k < 32; k++) {
        int d = lane + 32 * k;
        float xv = xr[d];
        xo[d] = __uint_as_float(f2tf(xv));
        float4 w0 = *(const float4*)(Wr + (size_t)d * 8);
        float4 w1 = *(const float4*)(Wr + (size_t)d * 8 + 4);
        acc[0] += xv * w0.x; acc[1] += xv * w0.y; acc[2] += xv * w0.z; acc[3] += xv * w0.w;
        acc[4] += xv * w1.x; acc[5] += xv * w1.y; acc[6] += xv * w1.z; acc[7] += xv * w1.w;
    }
#pragma unroll
    for (int off = 16; off > 0; off >>= 1)
#pragma unroll
        for (int e = 0; e < NE; e++)
            acc[e] += __shfl_down_sync(0xffffffffu, acc[e], off);

    if (lane == 0) {
        float m = acc[0]; int ai = 0;
#pragma unroll
        for (int e = 1; e < NE; e++) if (acc[e] > m) { m = acc[e]; ai = e; }
        float p[NE], s = 0.f;
#pragma unroll
        for (int e = 0; e < NE; e++) { p[e] = expf(acc[e] - m); s += p[e]; }
        float inv = 1.f / s;
        g_gate[t]   = p[ai] * inv;
        g_expert[t] = ai;
#pragma unroll
        for (int e = 0; e < NE; e++) atomicAdd(&s_ps[e], p[e] * inv);
        atomicAdd(&s_cnt[ai], 1);
    }
    __syncthreads();
    if (tid < NE) {
        atomicAdd(&g_psum[tid], s_ps[tid]);
        atomicAdd(&g_cnt[tid],  s_cnt[tid]);
    }
}

// ---------------- bucketize ----------------
__global__ void bucketize_kernel() {
    int t = blockIdx.x * blockDim.x + threadIdx.x;
    if (t >= T_TOK) return;
    int e = g_expert[t];
    int lane = threadIdx.x & 31;
    unsigned mask = __match_any_sync(0xffffffffu, e);
    int leader = __ffs(mask) - 1;
    int rank   = __popc(mask & ((1u << lane) - 1));
    int base = 0;
    if (lane == leader) base = atomicAdd(&g_bcnt[e], __popc(mask));
    base = __shfl_sync(0xffffffffu, base, leader);
    int pos = base + rank;
    g_btok[e][pos]  = t;
    g_bgate[e][pos] = g_gate[t];
}

// ---------------- capacity selection: 8 slices per expert ----------------
#define SEL_TPB 512
#define SEL_CHUNK 2048
#define SEL_SLICES 8
__global__ __launch_bounds__(SEL_TPB) void select_kernel() {
    int e = blockIdx.x >> 3;
    int slice = blockIdx.x & 7;
    int n = g_bcnt[e];
    __shared__ float sg[SEL_CHUNK];
    __shared__ int   stk[SEL_CHUNK];

    for (int i0 = slice * SEL_TPB; i0 < n; i0 += SEL_SLICES * SEL_TPB) {
        int i = i0 + threadIdx.x;
        bool active = (i < n);
        float g = 0.f; int t = 0; int rank = 0;
        if (active) { g = g_bgate[e][i]; t = g_btok[e][i]; }

        for (int c0 = 0; c0 < n; c0 += SEL_CHUNK) {
            int cn = min(SEL_CHUNK, n - c0);
            __syncthreads();
            for (int j = threadIdx.x; j < cn; j += SEL_TPB) {
                sg[j]  = g_bgate[e][c0 + j];
                stk[j] = g_btok[e][c0 + j];
            }
            __syncthreads();
            if (active) {
                for (int j = 0; j < cn; j++) {
                    float gj = sg[j];
                    if (gj > g || (gj == g && stk[j] < t)) rank++;
                }
            }
        }
        if (active && rank < CAP) {
            int pos = atomicAdd(&g_scnt[e], 1);
            g_stok[e][pos]  = t;
            g_sgate[e][pos] = g;
        }
        __syncthreads();
    }
}

// ---------------- pipelined tf32 mma.sync GEMM ----------------
// MODE 0: H = relu(Xg @ W1 + b1)   (K=DM,  N=DFF)
// MODE 1: out = gate*(H @ W2 + b2) (K=DFF, N=DM)
// CTA tile 128x256, BK=32, 8 warps (2m x 4n), warp tile 64x64, 2-stage cp.async.
template<int MODE>
__global__ void __launch_bounds__(256, 1) ffn_mma_kernel(const float* __restrict__ bias_all,
                                                         float* __restrict__ out)
{
    constexpr int KW  = MODE ? DFF : DM;   // reduction dim
    constexpr int NW  = MODE ? DM  : DFF;  // output width (B row length)
    constexpr int NKT = KW / BK;

    extern __shared__ float smem[];
    int e = blockIdx.z;
    int M = g_scnt[e];
    int m0 = blockIdx.y * BM;
    if (m0 >= M) return;
    int n0 = blockIdx.x * BN;

    int tid = threadIdx.x, wid = tid >> 5, lane = tid & 31;
    int gid = lane >> 2, tig = lane & 3;
    int m_base = (wid >> 2) * 64;   // 2 m-warps
    int n_base = (wid & 3) * 64;    // 4 n-warps

    uint32_t sbase = smem_u32(smem);
    const float* Wb = (MODE ? g_W2tf : g_W1tf) + (size_t)e * DM * DFF + n0;

    // ---- per-thread staging assignments ----
    const uint4* aptr[4]; uint32_t adst[4];
#pragma unroll
    for (int it = 0; it < 4; ++it) {
        int lin = tid + it * 256;
        int m = lin >> 3, q = lin & 7;
        int gm = m0 + m;
        int gmc = (gm < M) ? gm : 0;   // clamp: garbage rows masked in epilogue
        const float* row = (MODE == 0)
            ? (g_Xtf + (size_t)g_stok[e][gmc] * DM)
            : (g_H + ((size_t)e * CAP + gmc) * DFF);
        aptr[it] = (const uint4*)row + q;
        adst[it] = sbase + (uint32_t)(m * 9 + q) * 16;
    }
    const uint4* bptr[8]; uint32_t bdst[8];
#pragma unroll
    for (int it = 0; it < 8; ++it) {
        int lin = tid + it * 256;
        int k = lin >> 6, q = lin & 63;
        bptr[it] = (const uint4*)(Wb + (size_t)k * NW) + q;
        bdst[it] = sbase + (uint32_t)A_F * 4 + (uint32_t)(k * 66 + q) * 16;
    }

    float acc[4][8][4];
#pragma unroll
    for (int i = 0; i < 4; i++)
#pragma unroll
        for (int j = 0; j < 8; j++)
#pragma unroll
            for (int q = 0; q < 4; q++) acc[i][j][q] = 0.f;

    // ---- prologue: stage 0 ----
    {
#pragma unroll
        for (int it = 0; it < 4; ++it) cp16(adst[it], aptr[it]);
#pragma unroll
        for (int it = 0; it < 8; ++it) cp16(bdst[it], bptr[it]);
        cp_commit();
    }

    for (int kt = 0; kt < NKT; ++kt) {
        int buf = kt & 1;
        if (kt + 1 < NKT) {
            uint32_t soff = (uint32_t)((kt + 1) & 1) * (STAGE_F * 4);
            size_t ao = (size_t)(kt + 1) * 8;
            size_t bo = (size_t)(kt + 1) * 8 * NW;
#pragma unroll
            for (int it = 0; it < 4; ++it) cp16(adst[it] + soff, aptr[it] + ao);
#pragma unroll
            for (int it = 0; it < 8; ++it) cp16(bdst[it] + soff, bptr[it] + bo);
            cp_commit();
            cp_wait<1>();
        } else {
            cp_wait<0>();
        }
        __syncthreads();

        const float* As = smem + buf * STAGE_F;
        const float* Bs = As + A_F;

#pragma unroll
        for (int kk = 0; kk < 4; ++kk) {
            int k0 = kk * 8;
            unsigned a[4][4];
#pragma unroll
            for (int i = 0; i < 4; ++i) {
                int r = m_base + i * 16 + gid;
                a[i][0] = __float_as_uint(As[r * APITCH + k0 + tig]);
                a[i][1] = __float_as_uint(As[(r + 8) * APITCH + k0 + tig]);
                a[i][2] = __float_as_uint(As[r * APITCH + k0 + tig + 4]);
                a[i][3] = __float_as_uint(As[(r + 8) * APITCH + k0 + tig + 4]);
            }
            unsigned b[8][2];
#pragma unroll
            for (int j = 0; j < 8; ++j) {
                int c = n_base + j * 8 + gid;
                b[j][0] = __float_as_uint(Bs[(k0 + tig) * BPITCH + c]);
                b[j][1] = __float_as_uint(Bs[(k0 + tig + 4) * BPITCH + c]);
            }
#pragma unroll
            for (int i = 0; i < 4; ++i)
#pragma unroll
                for (int j = 0; j < 8; ++j)
                    mma_tf32(acc[i][j], a[i], b[j]);
        }
        __syncthreads();
    }

    // ---- epilogue ----
    const float* biasp = bias_all + (size_t)e * NW + n0;
#pragma unroll
    for (int i = 0; i < 4; ++i) {
        int m_lo = m0 + m_base + i * 16 + gid;
        int m_hi = m_lo + 8;
        bool lo_ok = (m_lo < M), hi_ok = (m_hi < M);

        int tok_lo = 0, tok_hi = 0; float gt_lo = 0.f, gt_hi = 0.f;
        if (MODE == 1) {
            if (lo_ok) { tok_lo = g_stok[e][m_lo]; gt_lo = g_sgate[e][m_lo]; }
            if (hi_ok) { tok_hi = g_stok[e][m_hi]; gt_hi = g_sgate[e][m_hi]; }
        }
#pragma unroll
        for (int j = 0; j < 8; ++j) {
            int nc = n_base + j * 8 + tig * 2;
            float bv0 = biasp[nc], bv1 = biasp[nc + 1];
            if (MODE == 0) {
                if (lo_ok) {
                    float2 o;
                    o.x = __uint_as_float(f2tf(fmaxf(acc[i][j][0] + bv0, 0.f)));
                    o.y = __uint_as_float(f2tf(fmaxf(acc[i][j][1] + bv1, 0.f)));
                    *(float2*)(g_H + ((size_t)e * CAP + m_lo) * DFF + n0 + nc) = o;
                }
                if (hi_ok) {
                    float2 o;
                    o.x = __uint_as_float(f2tf(fmaxf(acc[i][j][2] + bv0, 0.f)));
                    o.y = __uint_as_float(f2tf(fmaxf(acc[i][j][3] + bv1, 0.f)));
                    *(float2*)(g_H + ((size_t)e * CAP + m_hi) * DFF + n0 + nc) = o;
                }
            } else {
                if (lo_ok) {
                    float2 o;
                    o.x = gt_lo * (acc[i][j][0] + bv0);
                    o.y = gt_lo * (acc[i][j][1] + bv1);
                    *(float2*)(out + (size_t)tok_lo * DM + n0 + nc) = o;
                }
                if (hi_ok) {
                    float2 o;
                    o.x = gt_hi * (acc[i][j][2] + bv0);
                    o.y = gt_hi * (acc[i][j][3] + bv1);
                    *(float2*)(out + (size_t)tok_hi * DM + n0 + nc) = o;
                }
            }
        }
    }
}

// ---------------- load-balancing loss ----------------
__global__ void loss_kernel(float* __restrict__ out, int out_size) {
    if (out_size > T_TOK * DM) {
        float loss = 0.f;
#pragma unroll
        for (int e = 0; e < NE; e++)
            loss += ((float)g_cnt[e] / (float)T_TOK) * (g_psum[e] / (float)T_TOK);
        out[T_TOK * DM] = (float)NE * loss;
    }
}

// ---------------- launch ----------------
extern "C" void kernel_launch(void* const* d_in, const int* in_sizes, int n_in,
                              void* d_out, int out_size) {
    const float* x   = (const float*)d_in[0];
    const float* Wr  = (const float*)d_in[1];
    const float* W1  = (const float*)d_in[2];
    const float* b1  = (const float*)d_in[3];
    const float* W2  = (const float*)d_in[4];
    const float* b2  = (const float*)d_in[5];
    float* out = (float*)d_out;

    cudaFuncSetAttribute(ffn_mma_kernel<0>, cudaFuncAttributeMaxDynamicSharedMemorySize, SMEM_BYTES);
    cudaFuncSetAttribute(ffn_mma_kernel<1>, cudaFuncAttributeMaxDynamicSharedMemorySize, SMEM_BYTES);

    float* w1tf; cudaGetSymbolAddress((void**)&w1tf, g_W1tf);
    float* w2tf; cudaGetSymbolAddress((void**)&w2tf, g_W2tf);

    cudaMemsetAsync(d_out, 0, (size_t)out_size * sizeof(float));
    init_kernel<<<1, 32>>>();

    // pre-round weights to tf32 (layout unchanged)
    const size_t n4 = (size_t)NE * DM * DFF / 4;   // 8388608 float4s
    roundtf_kernel<<<(unsigned)(n4 / 256), 256>>>((const float4*)W1, (float4*)w1tf);
    roundtf_kernel<<<(unsigned)(n4 / 256), 256>>>((const float4*)W2, (float4*)w2tf);

    router_kernel<<<T_TOK / 8, 256>>>(x, Wr);
    bucketize_kernel<<<T_TOK / 256, 256>>>();
    select_kernel<<<NE * SEL_SLICES, SEL_TPB>>>();

    ffn_mma_kernel<0><<<dim3(DFF / BN, CAP / BM, NE), 256, SMEM_BYTES>>>(b1, nullptr);
    ffn_mma_kernel<1><<<dim3(DM / BN, CAP / BM, NE), 256, SMEM_BYTES>>>(b2, out);

    loss_kernel<<<1, 1>>>(out, out_size);
}

// round 5
// speedup vs baseline: 3.7844x; 1.0476x over previous
#include <cuda_runtime.h>
#include <cstdint>

#define T_TOK 8192
#define DM    1024
#define NE    8
#define CAP   1024
#define DFF   4096

#define BM 128
#define BN 256
#define BK 32
#define NSTAGE 3

#define APITCH 36           // floats per A smem row (pad 4)
#define BPITCH 264          // floats per B smem row (pad 8)
#define A_F (BM * APITCH)   // 4608 floats
#define B_F (BK * BPITCH)   // 8448 floats
#define STAGE_F (A_F + B_F) // 13056 floats
#define SMEM_BYTES (NSTAGE * STAGE_F * 4)  // 156672 bytes

// ---------------- scratch ----------------
__device__ float g_gate[T_TOK];
__device__ int   g_expert[T_TOK];
__device__ int   g_bcnt[NE];
__device__ int   g_btok[NE][T_TOK];
__device__ float g_bgate[NE][T_TOK];
__device__ int   g_scnt[NE];
__device__ int   g_stok[NE][CAP];
__device__ float g_sgate[NE][CAP];
__device__ float g_psum[NE];
__device__ int   g_cnt[NE];
__device__ float g_Xtf[(size_t)T_TOK * DM];        // x pre-rounded to tf32
__device__ float g_H[(size_t)NE * CAP * DFF];      // H, tf32-rounded

// ---------------- helpers ----------------
__device__ __forceinline__ unsigned f2tf(float f) {
    unsigned u; asm("cvt.rna.tf32.f32 %0, %1;" : "=r"(u) : "f"(f)); return u;
}
__device__ __forceinline__ uint32_t smem_u32(const void* p) {
    uint32_t a; asm("{ .reg .u64 t; cvta.to.shared.u64 t, %1; cvt.u32.u64 %0, t; }" : "=r"(a) : "l"(p));
    return a;
}
__device__ __forceinline__ void cp16(uint32_t dst, const void* src) {
    asm volatile("cp.async.cg.shared.global [%0], [%1], 16;" :: "r"(dst), "l"(src));
}
__device__ __forceinline__ void cp_commit() { asm volatile("cp.async.commit_group;"); }
template<int N> __device__ __forceinline__ void cp_wait() {
    asm volatile("cp.async.wait_group %0;" :: "n"(N));
}
__device__ __forceinline__ void mma_tf32(float* c, const unsigned* a, const unsigned* b) {
    asm volatile(
        "mma.sync.aligned.m16n8k8.row.col.f32.tf32.tf32.f32 "
        "{%0,%1,%2,%3},{%4,%5,%6,%7},{%8,%9},{%0,%1,%2,%3};"
        : "+f"(c[0]), "+f"(c[1]), "+f"(c[2]), "+f"(c[3])
        : "r"(a[0]), "r"(a[1]), "r"(a[2]), "r"(a[3]), "r"(b[0]), "r"(b[1]));
}

// ---------------- init ----------------
__global__ void init_kernel() {
    int i = threadIdx.x;
    if (i < NE) { g_bcnt[i] = 0; g_scnt[i] = 0; g_psum[i] = 0.f; g_cnt[i] = 0; }
}

// ---------------- router: one warp per token; writes tf32-rounded x ----------------
__global__ void router_kernel(const float* __restrict__ x, const float* __restrict__ Wr) {
    __shared__ float s_ps[NE];
    __shared__ int   s_cnt[NE];
    int tid = threadIdx.x;
    if (tid < NE) { s_ps[tid] = 0.f; s_cnt[tid] = 0; }
    __syncthreads();

    int warp = tid >> 5, lane = tid & 31;
    int t = blockIdx.x * 8 + warp;
    const float* xr = x + (size_t)t * DM;
    float* xo = g_Xtf + (size_t)t * DM;

    float acc[NE];
#pragma unroll
    for (int e = 0; e < NE; e++) acc[e] = 0.f;

#pragma unroll 8
    for (int k = 0; k < 32; k++) {
        int d = lane + 32 * k;
        float xv = xr[d];
        xo[d] = __uint_as_float(f2tf(xv));
        float4 w0 = *(const float4*)(Wr + (size_t)d * 8);
        float4 w1 = *(const float4*)(Wr + (size_t)d * 8 + 4);
        acc[0] += xv * w0.x; acc[1] += xv * w0.y; acc[2] += xv * w0.z; acc[3] += xv * w0.w;
        acc[4] += xv * w1.x; acc[5] += xv * w1.y; acc[6] += xv * w1.z; acc[7] += xv * w1.w;
    }
#pragma unroll
    for (int off = 16; off > 0; off >>= 1)
#pragma unroll
        for (int e = 0; e < NE; e++)
            acc[e] += __shfl_down_sync(0xffffffffu, acc[e], off);

    if (lane == 0) {
        float m = acc[0]; int ai = 0;
#pragma unroll
        for (int e = 1; e < NE; e++) if (acc[e] > m) { m = acc[e]; ai = e; }
        float p[NE], s = 0.f;
#pragma unroll
        for (int e = 0; e < NE; e++) { p[e] = expf(acc[e] - m); s += p[e]; }
        float inv = 1.f / s;
        g_gate[t]   = p[ai] * inv;
        g_expert[t] = ai;
#pragma unroll
        for (int e = 0; e < NE; e++) atomicAdd(&s_ps[e], p[e] * inv);
        atomicAdd(&s_cnt[ai], 1);
    }
    __syncthreads();
    if (tid < NE) {
        atomicAdd(&g_psum[tid], s_ps[tid]);
        atomicAdd(&g_cnt[tid],  s_cnt[tid]);
    }
}

// ---------------- bucketize ----------------
__global__ void bucketize_kernel() {
    int t = blockIdx.x * blockDim.x + threadIdx.x;
    if (t >= T_TOK) return;
    int e = g_expert[t];
    int lane = threadIdx.x & 31;
    unsigned mask = __match_any_sync(0xffffffffu, e);
    int leader = __ffs(mask) - 1;
    int rank   = __popc(mask & ((1u << lane) - 1));
    int base = 0;
    if (lane == leader) base = atomicAdd(&g_bcnt[e], __popc(mask));
    base = __shfl_sync(0xffffffffu, base, leader);
    int pos = base + rank;
    g_btok[e][pos]  = t;
    g_bgate[e][pos] = g_gate[t];
}

// ---------------- capacity selection: 8 slices per expert ----------------
#define SEL_TPB 512
#define SEL_CHUNK 2048
#define SEL_SLICES 8
__global__ __launch_bounds__(SEL_TPB) void select_kernel() {
    int e = blockIdx.x >> 3;
    int slice = blockIdx.x & 7;
    int n = g_bcnt[e];
    __shared__ float sg[SEL_CHUNK];
    __shared__ int   stk[SEL_CHUNK];

    for (int i0 = slice * SEL_TPB; i0 < n; i0 += SEL_SLICES * SEL_TPB) {
        int i = i0 + threadIdx.x;
        bool active = (i < n);
        float g = 0.f; int t = 0; int rank = 0;
        if (active) { g = g_bgate[e][i]; t = g_btok[e][i]; }

        for (int c0 = 0; c0 < n; c0 += SEL_CHUNK) {
            int cn = min(SEL_CHUNK, n - c0);
            __syncthreads();
            for (int j = threadIdx.x; j < cn; j += SEL_TPB) {
                sg[j]  = g_bgate[e][c0 + j];
                stk[j] = g_btok[e][c0 + j];
            }
            __syncthreads();
            if (active) {
                for (int j = 0; j < cn; j++) {
                    float gj = sg[j];
                    if (gj > g || (gj == g && stk[j] < t)) rank++;
                }
            }
        }
        if (active && rank < CAP) {
            int pos = atomicAdd(&g_scnt[e], 1);
            g_stok[e][pos]  = t;
            g_sgate[e][pos] = g;
        }
        __syncthreads();
    }
}

// ---------------- 3-stage pipelined tf32 mma.sync GEMM ----------------
// MODE 0: H = relu(Xg @ W1 + b1)   (K=DM,  N=DFF), A pre-rounded, B cvt in-loop
// MODE 1: out = gate*(H @ W2 + b2) (K=DFF, N=DM)
// CTA tile 128x256, BK=32, 8 warps (2m x 4n), warp tile 64x64.
template<int MODE>
__global__ void __launch_bounds__(256, 1) ffn_mma_kernel(const float* __restrict__ W,
                                                         const float* __restrict__ bias_all,
                                                         float* __restrict__ out)
{
    constexpr int KW  = MODE ? DFF : DM;   // reduction dim
    constexpr int NW  = MODE ? DM  : DFF;  // output width (B row length)
    constexpr int NKT = KW / BK;

    extern __shared__ float smem[];
    int e = blockIdx.z;
    int M = g_scnt[e];
    int m0 = blockIdx.y * BM;
    if (m0 >= M) return;
    int n0 = blockIdx.x * BN;

    int tid = threadIdx.x, wid = tid >> 5, lane = tid & 31;
    int gid = lane >> 2, tig = lane & 3;
    int m_base = (wid >> 2) * 64;   // 2 m-warps
    int n_base = (wid & 3) * 64;    // 4 n-warps

    uint32_t sbase = smem_u32(smem);
    const float* Wb = W + (size_t)e * DM * DFF + n0;   // raw fp32 weights

    // ---- per-thread staging assignments ----
    const uint4* aptr[4]; uint32_t adst[4];
#pragma unroll
    for (int it = 0; it < 4; ++it) {
        int lin = tid + it * 256;
        int m = lin >> 3, q = lin & 7;
        int gm = m0 + m;
        int gmc = (gm < M) ? gm : 0;   // clamp: garbage rows masked in epilogue
        const float* row = (MODE == 0)
            ? (g_Xtf + (size_t)g_stok[e][gmc] * DM)
            : (g_H + ((size_t)e * CAP + gmc) * DFF);
        aptr[it] = (const uint4*)row + q;
        adst[it] = sbase + (uint32_t)(m * 9 + q) * 16;
    }
    const uint4* bptr[8]; uint32_t bdst[8];
#pragma unroll
    for (int it = 0; it < 8; ++it) {
        int lin = tid + it * 256;
        int k = lin >> 6, q = lin & 63;
        bptr[it] = (const uint4*)(Wb + (size_t)k * NW) + q;
        bdst[it] = sbase + (uint32_t)A_F * 4 + (uint32_t)(k * 66 + q) * 16;
    }

    float acc[4][8][4];
#pragma unroll
    for (int i = 0; i < 4; i++)
#pragma unroll
        for (int j = 0; j < 8; j++)
#pragma unroll
            for (int q = 0; q < 4; q++) acc[i][j][q] = 0.f;

    // ---- prologue: stages 0, 1 ----
#pragma unroll
    for (int s = 0; s < 2; ++s) {
        uint32_t soff = (uint32_t)s * (STAGE_F * 4);
        size_t ao = (size_t)s * 8;
        size_t bo = (size_t)s * 8 * NW;
#pragma unroll
        for (int it = 0; it < 4; ++it) cp16(adst[it] + soff, aptr[it] + ao);
#pragma unroll
        for (int it = 0; it < 8; ++it) cp16(bdst[it] + soff, bptr[it] + bo);
        cp_commit();
    }

    for (int kt = 0; kt < NKT; ++kt) {
        // stage kt+2 (buffer last read in compute kt-1; protected by prev-iter end sync)
        if (kt + 2 < NKT) {
            int s = (kt + 2) % NSTAGE;
            uint32_t soff = (uint32_t)s * (STAGE_F * 4);
            size_t ao = (size_t)(kt + 2) * 8;
            size_t bo = (size_t)(kt + 2) * 8 * NW;
#pragma unroll
            for (int it = 0; it < 4; ++it) cp16(adst[it] + soff, aptr[it] + ao);
#pragma unroll
            for (int it = 0; it < 8; ++it) cp16(bdst[it] + soff, bptr[it] + bo);
        }
        cp_commit();            // (possibly empty) — keeps group accounting uniform
        cp_wait<2>();           // stage kt complete
        __syncthreads();

        const float* As = smem + (kt % NSTAGE) * STAGE_F;
        const float* Bs = As + A_F;

#pragma unroll
        for (int kk = 0; kk < 4; ++kk) {
            int k0 = kk * 8;
            unsigned a[4][4];
#pragma unroll
            for (int i = 0; i < 4; ++i) {
                int r = m_base + i * 16 + gid;
                a[i][0] = __float_as_uint(As[r * APITCH + k0 + tig]);
                a[i][1] = __float_as_uint(As[(r + 8) * APITCH + k0 + tig]);
                a[i][2] = __float_as_uint(As[r * APITCH + k0 + tig + 4]);
                a[i][3] = __float_as_uint(As[(r + 8) * APITCH + k0 + tig + 4]);
            }
            unsigned b[8][2];
#pragma unroll
            for (int j = 0; j < 8; ++j) {
                int c = n_base + j * 8 + gid;
                b[j][0] = f2tf(Bs[(k0 + tig) * BPITCH + c]);       // rna rounding on fragment
                b[j][1] = f2tf(Bs[(k0 + tig + 4) * BPITCH + c]);
            }
#pragma unroll
            for (int i = 0; i < 4; ++i)
#pragma unroll
                for (int j = 0; j < 8; ++j)
                    mma_tf32(acc[i][j], a[i], b[j]);
        }
        __syncthreads();        // protect buf kt%3 before iter kt+1 overwrites it
    }

    // ---- epilogue ----
    const float* biasp = bias_all + (size_t)e * NW + n0;
#pragma unroll
    for (int i = 0; i < 4; ++i) {
        int m_lo = m0 + m_base + i * 16 + gid;
        int m_hi = m_lo + 8;
        bool lo_ok = (m_lo < M), hi_ok = (m_hi < M);

        int tok_lo = 0, tok_hi = 0; float gt_lo = 0.f, gt_hi = 0.f;
        if (MODE == 1) {
            if (lo_ok) { tok_lo = g_stok[e][m_lo]; gt_lo = g_sgate[e][m_lo]; }
            if (hi_ok) { tok_hi = g_stok[e][m_hi]; gt_hi = g_sgate[e][m_hi]; }
        }
#pragma unroll
        for (int j = 0; j < 8; ++j) {
            int nc = n_base + j * 8 + tig * 2;
            float bv0 = biasp[nc], bv1 = biasp[nc + 1];
            if (MODE == 0) {
                if (lo_ok) {
                    float2 o;
                    o.x = __uint_as_float(f2tf(fmaxf(acc[i][j][0] + bv0, 0.f)));
                    o.y = __uint_as_float(f2tf(fmaxf(acc[i][j][1] + bv1, 0.f)));
                    *(float2*)(g_H + ((size_t)e * CAP + m_lo) * DFF + n0 + nc) = o;
                }
                if (hi_ok) {
                    float2 o;
                    o.x = __uint_as_float(f2tf(fmaxf(acc[i][j][2] + bv0, 0.f)));
                    o.y = __uint_as_float(f2tf(fmaxf(acc[i][j][3] + bv1, 0.f)));
                    *(float2*)(g_H + ((size_t)e * CAP + m_hi) * DFF + n0 + nc) = o;
                }
            } else {
                if (lo_ok) {
                    float2 o;
                    o.x = gt_lo * (acc[i][j][0] + bv0);
                    o.y = gt_lo * (acc[i][j][1] + bv1);
                    *(float2*)(out + (size_t)tok_lo * DM + n0 + nc) = o;
                }
                if (hi_ok) {
                    float2 o;
                    o.x = gt_hi * (acc[i][j][2] + bv0);
                    o.y = gt_hi * (acc[i][j][3] + bv1);
                    *(float2*)(out + (size_t)tok_hi * DM + n0 + nc) = o;
                }
            }
        }
    }
}

// ---------------- load-balancing loss ----------------
__global__ void loss_kernel(float* __restrict__ out, int out_size) {
    if (out_size > T_TOK * DM) {
        float loss = 0.f;
#pragma unroll
        for (int e = 0; e < NE; e++)
            loss += ((float)g_cnt[e] / (float)T_TOK) * (g_psum[e] / (float)T_TOK);
        out[T_TOK * DM] = (float)NE * loss;
    }
}

// ---------------- launch ----------------
extern "C" void kernel_launch(void* const* d_in, const int* in_sizes, int n_in,
                              void* d_out, int out_size) {
    const float* x   = (const float*)d_in[0];
    const float* Wr  = (const float*)d_in[1];
    const float* W1  = (const float*)d_in[2];
    const float* b1  = (const float*)d_in[3];
    const float* W2  = (const float*)d_in[4];
    const float* b2  = (const float*)d_in[5];
    float* out = (float*)d_out;

    cudaFuncSetAttribute(ffn_mma_kernel<0>, cudaFuncAttributeMaxDynamicSharedMemorySize, SMEM_BYTES);
    cudaFuncSetAttribute(ffn_mma_kernel<1>, cudaFuncAttributeMaxDynamicSharedMemorySize, SMEM_BYTES);

    cudaMemsetAsync(d_out, 0, (size_t)out_size * sizeof(float));
    init_kernel<<<1, 32>>>();

    router_kernel<<<T_TOK / 8, 256>>>(x, Wr);
    bucketize_kernel<<<T_TOK / 256, 256>>>();
    select_kernel<<<NE * SEL_SLICES, SEL_TPB>>>();

    ffn_mma_kernel<0><<<dim3(DFF / BN, CAP / BM, NE), 256, SMEM_BYTES>>>(W1, b1, nullptr);
    ffn_mma_kernel<1><<<dim3(DM / BN, CAP / BM, NE), 256, SMEM_BYTES>>>(W2, b2, out);

    loss_kernel<<<1, 1>>>(out, out_size);
}

// round 6
// speedup vs baseline: 5.5129x; 1.4567x over previous
#include <cuda_runtime.h>
#include <cuda_fp16.h>
#include <cstdint>

#define T_TOK 8192
#define DM    1024
#define NE    8
#define CAP   1024
#define DFF   4096

#define BM 128
#define BN 256
#define BK 32
#define NSTAGE 4

#define APITCH_H 40                      // halves per A smem row (32 data + 8 pad)
#define BPITCH_H 264                     // halves per B smem row (256 data + 8 pad)
#define A_BYTES (BM * APITCH_H * 2)      // 10240
#define B_BYTES (BK * BPITCH_H * 2)      // 16896
#define STAGE_BYTES (A_BYTES + B_BYTES)  // 27136
#define SMEM_BYTES (NSTAGE * STAGE_BYTES) // 108544

// ---------------- scratch ----------------
__device__ float  g_gate[T_TOK];
__device__ int    g_expert[T_TOK];
__device__ int    g_bcnt[NE];
__device__ int    g_btok[NE][T_TOK];
__device__ float  g_bgate[NE][T_TOK];
__device__ int    g_scnt[NE];
__device__ int    g_stok[NE][CAP];
__device__ float  g_sgate[NE][CAP];
__device__ float  g_psum[NE];
__device__ int    g_cnt[NE];
__device__ __half g_Xh[(size_t)T_TOK * DM];       // x in fp16
__device__ __half g_W1h[(size_t)NE * DM * DFF];   // W1 fp16, [e][k][n]
__device__ __half g_W2h[(size_t)NE * DFF * DM];   // W2 fp16, [e][k][n]
__device__ __half g_H[(size_t)NE * CAP * DFF];    // H fp16

// ---------------- helpers ----------------
__device__ __forceinline__ uint32_t smem_u32(const void* p) {
    uint32_t a; asm("{ .reg .u64 t; cvta.to.shared.u64 t, %1; cvt.u32.u64 %0, t; }" : "=r"(a) : "l"(p));
    return a;
}
__device__ __forceinline__ void cp16(uint32_t dst, const void* src) {
    asm volatile("cp.async.cg.shared.global [%0], [%1], 16;" :: "r"(dst), "l"(src));
}
__device__ __forceinline__ void cp_commit() { asm volatile("cp.async.commit_group;"); }
template<int N> __device__ __forceinline__ void cp_wait() {
    asm volatile("cp.async.wait_group %0;" :: "n"(N));
}
__device__ __forceinline__ void ldsm_x4(unsigned& r0, unsigned& r1, unsigned& r2, unsigned& r3,
                                        uint32_t addr) {
    asm volatile("ldmatrix.sync.aligned.m8n8.x4.shared.b16 {%0,%1,%2,%3}, [%4];"
                 : "=r"(r0), "=r"(r1), "=r"(r2), "=r"(r3) : "r"(addr));
}
__device__ __forceinline__ void ldsm_x4_t(unsigned& r0, unsigned& r1, unsigned& r2, unsigned& r3,
                                          uint32_t addr) {
    asm volatile("ldmatrix.sync.aligned.m8n8.x4.trans.shared.b16 {%0,%1,%2,%3}, [%4];"
                 : "=r"(r0), "=r"(r1), "=r"(r2), "=r"(r3) : "r"(addr));
}
__device__ __forceinline__ void mma_f16(float* c, const unsigned* a, const unsigned* b) {
    asm volatile(
        "mma.sync.aligned.m16n8k16.row.col.f32.f16.f16.f32 "
        "{%0,%1,%2,%3},{%4,%5,%6,%7},{%8,%9},{%0,%1,%2,%3};"
        : "+f"(c[0]), "+f"(c[1]), "+f"(c[2]), "+f"(c[3])
        : "r"(a[0]), "r"(a[1]), "r"(a[2]), "r"(a[3]), "r"(b[0]), "r"(b[1]));
}

// ---------------- init ----------------
__global__ void init_kernel() {
    int i = threadIdx.x;
    if (i < NE) { g_bcnt[i] = 0; g_scnt[i] = 0; g_psum[i] = 0.f; g_cnt[i] = 0; }
}

// ---------------- fp32 -> fp16 weight convert (8 elems/thread) ----------------
__global__ void f2h_kernel(const float4* __restrict__ src, uint4* __restrict__ dst) {
    size_t i = (size_t)blockIdx.x * blockDim.x + threadIdx.x;
    float4 v0 = src[2 * i], v1 = src[2 * i + 1];
    __half2 h0 = __floats2half2_rn(v0.x, v0.y);
    __half2 h1 = __floats2half2_rn(v0.z, v0.w);
    __half2 h2 = __floats2half2_rn(v1.x, v1.y);
    __half2 h3 = __floats2half2_rn(v1.z, v1.w);
    uint4 u;
    u.x = *reinterpret_cast<unsigned*>(&h0);
    u.y = *reinterpret_cast<unsigned*>(&h1);
    u.z = *reinterpret_cast<unsigned*>(&h2);
    u.w = *reinterpret_cast<unsigned*>(&h3);
    dst[i] = u;
}

// ---------------- router: one warp per token; writes fp16 x ----------------
__global__ void router_kernel(const float* __restrict__ x, const float* __restrict__ Wr) {
    __shared__ float s_ps[NE];
    __shared__ int   s_cnt[NE];
    int tid = threadIdx.x;
    if (tid < NE) { s_ps[tid] = 0.f; s_cnt[tid] = 0; }
    __syncthreads();

    int warp = tid >> 5, lane = tid & 31;
    int t = blockIdx.x * 8 + warp;
    const float* xr = x + (size_t)t * DM;
    __half* xo = g_Xh + (size_t)t * DM;

    float acc[NE];
#pragma unroll
    for (int e = 0; e < NE; e++) acc[e] = 0.f;

#pragma unroll 8
    for (int k = 0; k < 32; k++) {
        int d = lane + 32 * k;
        float xv = xr[d];
        xo[d] = __float2half_rn(xv);
        float4 w0 = *(const float4*)(Wr + (size_t)d * 8);
        float4 w1 = *(const float4*)(Wr + (size_t)d * 8 + 4);
        acc[0] += xv * w0.x; acc[1] += xv * w0.y; acc[2] += xv * w0.z; acc[3] += xv * w0.w;
        acc[4] += xv * w1.x; acc[5] += xv * w1.y; acc[6] += xv * w1.z; acc[7] += xv * w1.w;
    }
#pragma unroll
    for (int off = 16; off > 0; off >>= 1)
#pragma unroll
        for (int e = 0; e < NE; e++)
            acc[e] += __shfl_down_sync(0xffffffffu, acc[e], off);

    if (lane == 0) {
        float m = acc[0]; int ai = 0;
#pragma unroll
        for (int e = 1; e < NE; e++) if (acc[e] > m) { m = acc[e]; ai = e; }
        float p[NE], s = 0.f;
#pragma unroll
        for (int e = 0; e < NE; e++) { p[e] = expf(acc[e] - m); s += p[e]; }
        float inv = 1.f / s;
        g_gate[t]   = p[ai] * inv;
        g_expert[t] = ai;
#pragma unroll
        for (int e = 0; e < NE; e++) atomicAdd(&s_ps[e], p[e] * inv);
        atomicAdd(&s_cnt[ai], 1);
    }
    __syncthreads();
    if (tid < NE) {
        atomicAdd(&g_psum[tid], s_ps[tid]);
        atomicAdd(&g_cnt[tid],  s_cnt[tid]);
    }
}

// ---------------- bucketize ----------------
__global__ void bucketize_kernel() {
    int t = blockIdx.x * blockDim.x + threadIdx.x;
    if (t >= T_TOK) return;
    int e = g_expert[t];
    int lane = threadIdx.x & 31;
    unsigned mask = __match_any_sync(0xffffffffu, e);
    int leader = __ffs(mask) - 1;
    int rank   = __popc(mask & ((1u << lane) - 1));
    int base = 0;
    if (lane == leader) base = atomicAdd(&g_bcnt[e], __popc(mask));
    base = __shfl_sync(0xffffffffu, base, leader);
    int pos = base + rank;
    g_btok[e][pos]  = t;
    g_bgate[e][pos] = g_gate[t];
}

// ---------------- capacity selection: 8 slices per expert ----------------
#define SEL_TPB 512
#define SEL_CHUNK 2048
#define SEL_SLICES 8
__global__ __launch_bounds__(SEL_TPB) void select_kernel() {
    int e = blockIdx.x >> 3;
    int slice = blockIdx.x & 7;
    int n = g_bcnt[e];
    __shared__ float sg[SEL_CHUNK];
    __shared__ int   stk[SEL_CHUNK];

    for (int i0 = slice * SEL_TPB; i0 < n; i0 += SEL_SLICES * SEL_TPB) {
        int i = i0 + threadIdx.x;
        bool active = (i < n);
        float g = 0.f; int t = 0; int rank = 0;
        if (active) { g = g_bgate[e][i]; t = g_btok[e][i]; }

        for (int c0 = 0; c0 < n; c0 += SEL_CHUNK) {
            int cn = min(SEL_CHUNK, n - c0);
            __syncthreads();
            for (int j = threadIdx.x; j < cn; j += SEL_TPB) {
                sg[j]  = g_bgate[e][c0 + j];
                stk[j] = g_btok[e][c0 + j];
            }
            __syncthreads();
            if (active) {
                for (int j = 0; j < cn; j++) {
                    float gj = sg[j];
                    if (gj > g || (gj == g && stk[j] < t)) rank++;
                }
            }
        }
        if (active && rank < CAP) {
            int pos = atomicAdd(&g_scnt[e], 1);
            g_stok[e][pos]  = t;
            g_sgate[e][pos] = g;
        }
        __syncthreads();
    }
}

// ---------------- 4-stage pipelined fp16 mma.sync GEMM ----------------
// MODE 0: H = relu(Xg @ W1 + b1)   (K=DM,  N=DFF)
// MODE 1: out = gate*(H @ W2 + b2) (K=DFF, N=DM)
// CTA 128x256, BK=32, 8 warps (2m x 4n), warp tile 64x64, ldmatrix fragments.
template<int MODE>
__global__ void __launch_bounds__(256, 1) ffn_mma_kernel(const float* __restrict__ bias_all,
                                                         float* __restrict__ out)
{
    constexpr int KW  = MODE ? DFF : DM;
    constexpr int NW  = MODE ? DM  : DFF;
    constexpr int NKT = KW / BK;

    extern __shared__ char smem[];
    int e = blockIdx.z;
    int M = g_scnt[e];
    int m0 = blockIdx.y * BM;
    if (m0 >= M) return;
    int n0 = blockIdx.x * BN;

    int tid = threadIdx.x, wid = tid >> 5, lane = tid & 31;
    int gid = lane >> 2, tig = lane & 3;
    int quad = lane >> 3, lr = lane & 7;
    int m_base = (wid >> 2) * 64;   // 2 m-warps
    int n_base = (wid & 3) * 64;    // 4 n-warps

    uint32_t sbase = smem_u32(smem);
    const __half* Wbh = (MODE ? g_W2h : g_W1h) + (size_t)e * DM * DFF + n0;

    // ---- staging assignments ----
    // A: 128 rows x 32 halves (4 x 16B chunks/row); 512 chunks, 2/thread
    const uint4* aptr[2]; uint32_t adst[2];
#pragma unroll
    for (int it = 0; it < 2; ++it) {
        int lin = tid + it * 256;
        int m = lin >> 2, q = lin & 3;
        int gm = m0 + m;
        int gmc = (gm < M) ? gm : 0;
        const __half* row = (MODE == 0)
            ? (g_Xh + (size_t)g_stok[e][gmc] * DM)
            : (g_H + ((size_t)e * CAP + gmc) * DFF);
        aptr[it] = (const uint4*)row + q;
        adst[it] = sbase + (uint32_t)(m * APITCH_H + q * 8) * 2;
    }
    // B: 32 rows(k) x 256 halves (32 x 16B chunks/row); 1024 chunks, 4/thread
    const uint4* bptr[4]; uint32_t bdst[4];
#pragma unroll
    for (int it = 0; it < 4; ++it) {
        int lin = tid + it * 256;
        int k = lin >> 5, q = lin & 31;
        bptr[it] = (const uint4*)(Wbh + (size_t)k * NW) + q;
        bdst[it] = sbase + A_BYTES + (uint32_t)(k * BPITCH_H + q * 8) * 2;
    }

    // ---- ldmatrix base addresses ----
    uint32_t a_addr[4];
#pragma unroll
    for (int i = 0; i < 4; ++i) {
        int row = m_base + i * 16 + (quad & 1) * 8 + lr;
        int col = (quad >> 1) * 8;
        a_addr[i] = sbase + (uint32_t)(row * APITCH_H + col) * 2;
    }
    uint32_t b_addr[4];
#pragma unroll
    for (int jj = 0; jj < 4; ++jj) {
        int k = (quad & 1) * 8 + lr;
        int n = n_base + (2 * jj + (quad >> 1)) * 8;
        b_addr[jj] = sbase + A_BYTES + (uint32_t)(k * BPITCH_H + n) * 2;
    }

    float acc[4][8][4];
#pragma unroll
    for (int i = 0; i < 4; i++)
#pragma unroll
        for (int j = 0; j < 8; j++)
#pragma unroll
            for (int q = 0; q < 4; q++) acc[i][j][q] = 0.f;

    // ---- prologue: stages 0..2 ----
#pragma unroll
    for (int s = 0; s < NSTAGE - 1; ++s) {
        uint32_t soff = (uint32_t)s * STAGE_BYTES;
        size_t ao = (size_t)s * 4;            // 4 uint4 per kt (A row advance 32 halves)
        size_t bo = (size_t)s * 4 * NW / 8 * 2; // 32 rows * NW halves = 4*NW uint4... computed below
#pragma unroll
        for (int it = 0; it < 2; ++it) cp16(adst[it] + soff, aptr[it] + ao);
#pragma unroll
        for (int it = 0; it < 4; ++it) cp16(bdst[it] + soff, bptr[it] + (size_t)s * 4 * NW);
        (void)bo;
        cp_commit();
    }

    for (int kt = 0; kt < NKT; ++kt) {
        if (kt + NSTAGE - 1 < NKT) {
            int s = (kt + NSTAGE - 1) % NSTAGE;
            uint32_t soff = (uint32_t)s * STAGE_BYTES;
            size_t ao = (size_t)(kt + NSTAGE - 1) * 4;
            size_t bo = (size_t)(kt + NSTAGE - 1) * 4 * NW;
#pragma unroll
            for (int it = 0; it < 2; ++it) cp16(adst[it] + soff, aptr[it] + ao);
#pragma unroll
            for (int it = 0; it < 4; ++it) cp16(bdst[it] + soff, bptr[it] + bo);
        }
        cp_commit();
        cp_wait<NSTAGE - 1>();
        __syncthreads();

        uint32_t soff = (uint32_t)(kt % NSTAGE) * STAGE_BYTES;

#pragma unroll
        for (int kk = 0; kk < 2; ++kk) {      // two k16 chunks per BK=32
            uint32_t akoff = soff + kk * 16 * 2;            // +16 halves along k
            uint32_t bkoff = soff + kk * 16 * BPITCH_H * 2; // +16 k-rows
            unsigned A_[4][4];
#pragma unroll
            for (int i = 0; i < 4; ++i)
                ldsm_x4(A_[i][0], A_[i][1], A_[i][2], A_[i][3], a_addr[i] + akoff);
            unsigned B_[8][2];
#pragma unroll
            for (int jj = 0; jj < 4; ++jj)
                ldsm_x4_t(B_[2 * jj][0], B_[2 * jj][1], B_[2 * jj + 1][0], B_[2 * jj + 1][1],
                          b_addr[jj] + bkoff);
#pragma unroll
            for (int i = 0; i < 4; ++i)
#pragma unroll
                for (int j = 0; j < 8; ++j)
                    mma_f16(acc[i][j], A_[i], B_[j]);
        }
        __syncthreads();
    }

    // ---- epilogue ----
    const float* biasp = bias_all + (size_t)e * NW + n0;
#pragma unroll
    for (int i = 0; i < 4; ++i) {
        int m_lo = m0 + m_base + i * 16 + gid;
        int m_hi = m_lo + 8;
        bool lo_ok = (m_lo < M), hi_ok = (m_hi < M);

        int tok_lo = 0, tok_hi = 0; float gt_lo = 0.f, gt_hi = 0.f;
        if (MODE == 1) {
            if (lo_ok) { tok_lo = g_stok[e][m_lo]; gt_lo = g_sgate[e][m_lo]; }
            if (hi_ok) { tok_hi = g_stok[e][m_hi]; gt_hi = g_sgate[e][m_hi]; }
        }
#pragma unroll
        for (int j = 0; j < 8; ++j) {
            int nc = n_base + j * 8 + tig * 2;
            float bv0 = biasp[nc], bv1 = biasp[nc + 1];
            if (MODE == 0) {
                if (lo_ok) {
                    __half2 o = __floats2half2_rn(fmaxf(acc[i][j][0] + bv0, 0.f),
                                                  fmaxf(acc[i][j][1] + bv1, 0.f));
                    *(__half2*)(g_H + ((size_t)e * CAP + m_lo) * DFF + n0 + nc) = o;
                }
                if (hi_ok) {
                    __half2 o = __floats2half2_rn(fmaxf(acc[i][j][2] + bv0, 0.f),
                                                  fmaxf(acc[i][j][3] + bv1, 0.f));
                    *(__half2*)(g_H + ((size_t)e * CAP + m_hi) * DFF + n0 + nc) = o;
                }
            } else {
                if (lo_ok) {
                    float2 o;
                    o.x = gt_lo * (acc[i][j][0] + bv0);
                    o.y = gt_lo * (acc[i][j][1] + bv1);
                    *(float2*)(out + (size_t)tok_lo * DM + n0 + nc) = o;
                }
                if (hi_ok) {
                    float2 o;
                    o.x = gt_hi * (acc[i][j][2] + bv0);
                    o.y = gt_hi * (acc[i][j][3] + bv1);
                    *(float2*)(out + (size_t)tok_hi * DM + n0 + nc) = o;
                }
            }
        }
    }
}

// ---------------- load-balancing loss ----------------
__global__ void loss_kernel(float* __restrict__ out, int out_size) {
    if (out_size > T_TOK * DM) {
        float loss = 0.f;
#pragma unroll
        for (int e = 0; e < NE; e++)
            loss += ((float)g_cnt[e] / (float)T_TOK) * (g_psum[e] / (float)T_TOK);
        out[T_TOK * DM] = (float)NE * loss;
    }
}

// ---------------- launch ----------------
extern "C" void kernel_launch(void* const* d_in, const int* in_sizes, int n_in,
                              void* d_out, int out_size) {
    const float* x   = (const float*)d_in[0];
    const float* Wr  = (const float*)d_in[1];
    const float* W1  = (const float*)d_in[2];
    const float* b1  = (const float*)d_in[3];
    const float* W2  = (const float*)d_in[4];
    const float* b2  = (const float*)d_in[5];
    float* out = (float*)d_out;

    cudaFuncSetAttribute(ffn_mma_kernel<0>, cudaFuncAttributeMaxDynamicSharedMemorySize, SMEM_BYTES);
    cudaFuncSetAttribute(ffn_mma_kernel<1>, cudaFuncAttributeMaxDynamicSharedMemorySize, SMEM_BYTES);

    void* w1h; cudaGetSymbolAddress(&w1h, g_W1h);
    void* w2h; cudaGetSymbolAddress(&w2h, g_W2h);

    cudaMemsetAsync(d_out, 0, (size_t)out_size * sizeof(float));
    init_kernel<<<1, 32>>>();

    // weights fp32 -> fp16 (8 elems/thread)
    const unsigned nthr = (unsigned)((size_t)NE * DM * DFF / 8);
    f2h_kernel<<<nthr / 256, 256>>>((const float4*)W1, (uint4*)w1h);
    f2h_kernel<<<nthr / 256, 256>>>((const float4*)W2, (uint4*)w2h);

    router_kernel<<<T_TOK / 8, 256>>>(x, Wr);
    bucketize_kernel<<<T_TOK / 256, 256>>>();
    select_kernel<<<NE * SEL_SLICES, SEL_TPB>>>();

    ffn_mma_kernel<0><<<dim3(DFF / BN, CAP / BM, NE), 256, SMEM_BYTES>>>(b1, nullptr);
    ffn_mma_kernel<1><<<dim3(DM / BN, CAP / BM, NE), 256, SMEM_BYTES>>>(b2, out);

    loss_kernel<<<1, 1>>>(out, out_size);
}

// round 7
// speedup vs baseline: 6.0436x; 1.0963x over previous
#include <cuda_runtime.h>
#include <cuda_fp16.h>
#include <cstdint>

#define T_TOK 8192
#define DM    1024
#define NE    8
#define CAP   1024
#define DFF   4096

#define BM 128
#define BN 256
#define BK 32
#define NSTAGE 4

#define APITCH_H 40                      // halves per A smem row (32 data + 8 pad)
#define BPITCH_H 264                     // halves per B smem row (256 data + 8 pad)
#define A_BYTES (BM * APITCH_H * 2)      // 10240
#define B_BYTES (BK * BPITCH_H * 2)      // 16896
#define STAGE_BYTES (A_BYTES + B_BYTES)  // 27136
#define SMEM_BYTES (NSTAGE * STAGE_BYTES) // 108544

// ---------------- scratch ----------------
__device__ float  g_gate[T_TOK];
__device__ int    g_expert[T_TOK];
__device__ int    g_bcnt[NE];
__device__ int    g_btok[NE][T_TOK];
__device__ float  g_bgate[NE][T_TOK];
__device__ int    g_srt_tok[NE][T_TOK];
__device__ float  g_srt_gate[NE][T_TOK];
__device__ int    g_scnt[NE];
__device__ int    g_stok[NE][CAP];
__device__ float  g_sgate[NE][CAP];
__device__ float  g_psum[NE];
__device__ int    g_cnt[NE];
__device__ __half g_Xh[(size_t)T_TOK * DM];       // x in fp16
__device__ __half g_W1h[(size_t)NE * DM * DFF];   // W1 fp16, [e][k][n]
__device__ __half g_W2h[(size_t)NE * DFF * DM];   // W2 fp16, [e][k][n]
__device__ __half g_H[(size_t)NE * CAP * DFF];    // H fp16

// ---------------- helpers ----------------
__device__ __forceinline__ uint32_t smem_u32(const void* p) {
    uint32_t a; asm("{ .reg .u64 t; cvta.to.shared.u64 t, %1; cvt.u32.u64 %0, t; }" : "=r"(a) : "l"(p));
    return a;
}
__device__ __forceinline__ void cp16(uint32_t dst, const void* src) {
    asm volatile("cp.async.cg.shared.global [%0], [%1], 16;" :: "r"(dst), "l"(src));
}
__device__ __forceinline__ void cp_commit() { asm volatile("cp.async.commit_group;"); }
template<int N> __device__ __forceinline__ void cp_wait() {
    asm volatile("cp.async.wait_group %0;" :: "n"(N));
}
__device__ __forceinline__ void ldsm_x4(unsigned& r0, unsigned& r1, unsigned& r2, unsigned& r3,
                                        uint32_t addr) {
    asm volatile("ldmatrix.sync.aligned.m8n8.x4.shared.b16 {%0,%1,%2,%3}, [%4];"
                 : "=r"(r0), "=r"(r1), "=r"(r2), "=r"(r3) : "r"(addr));
}
__device__ __forceinline__ void ldsm_x4_t(unsigned& r0, unsigned& r1, unsigned& r2, unsigned& r3,
                                          uint32_t addr) {
    asm volatile("ldmatrix.sync.aligned.m8n8.x4.trans.shared.b16 {%0,%1,%2,%3}, [%4];"
                 : "=r"(r0), "=r"(r1), "=r"(r2), "=r"(r3) : "r"(addr));
}
__device__ __forceinline__ void mma_f16(float* c, const unsigned* a, const unsigned* b) {
    asm volatile(
        "mma.sync.aligned.m16n8k16.row.col.f32.f16.f16.f32 "
        "{%0,%1,%2,%3},{%4,%5,%6,%7},{%8,%9},{%0,%1,%2,%3};"
        : "+f"(c[0]), "+f"(c[1]), "+f"(c[2]), "+f"(c[3])
        : "r"(a[0]), "r"(a[1]), "r"(a[2]), "r"(a[3]), "r"(b[0]), "r"(b[1]));
}

// ---------------- init ----------------
__global__ void init_kernel() {
    int i = threadIdx.x;
    if (i < NE) { g_bcnt[i] = 0; g_scnt[i] = 0; g_psum[i] = 0.f; g_cnt[i] = 0; }
}

// ---------------- fp32 -> fp16 weight convert (8 elems/thread) ----------------
__global__ void f2h_kernel(const float4* __restrict__ src, uint4* __restrict__ dst) {
    size_t i = (size_t)blockIdx.x * blockDim.x + threadIdx.x;
    float4 v0 = src[2 * i], v1 = src[2 * i + 1];
    __half2 h0 = __floats2half2_rn(v0.x, v0.y);
    __half2 h1 = __floats2half2_rn(v0.z, v0.w);
    __half2 h2 = __floats2half2_rn(v1.x, v1.y);
    __half2 h3 = __floats2half2_rn(v1.z, v1.w);
    uint4 u;
    u.x = *reinterpret_cast<unsigned*>(&h0);
    u.y = *reinterpret_cast<unsigned*>(&h1);
    u.z = *reinterpret_cast<unsigned*>(&h2);
    u.w = *reinterpret_cast<unsigned*>(&h3);
    dst[i] = u;
}

// ---------------- router: one warp per token, float4 loads; writes fp16 x ----------------
__global__ void router_kernel(const float* __restrict__ x, const float* __restrict__ Wr) {
    __shared__ float s_ps[NE];
    __shared__ int   s_cnt[NE];
    int tid = threadIdx.x;
    if (tid < NE) { s_ps[tid] = 0.f; s_cnt[tid] = 0; }
    __syncthreads();

    int warp = tid >> 5, lane = tid & 31;
    int t = blockIdx.x * 8 + warp;
    const float* xr = x + (size_t)t * DM;
    __half* xo = g_Xh + (size_t)t * DM;

    float acc[NE];
#pragma unroll
    for (int e = 0; e < NE; e++) acc[e] = 0.f;

#pragma unroll
    for (int k = 0; k < 8; k++) {
        int d = lane * 4 + 128 * k;
        float4 xv = *(const float4*)(xr + d);
        __half2 ha = __floats2half2_rn(xv.x, xv.y);
        __half2 hb = __floats2half2_rn(xv.z, xv.w);
        uint2 u;
        u.x = *reinterpret_cast<unsigned*>(&ha);
        u.y = *reinterpret_cast<unsigned*>(&hb);
        *(uint2*)(xo + d) = u;
        float xq[4] = {xv.x, xv.y, xv.z, xv.w};
#pragma unroll
        for (int q = 0; q < 4; q++) {
            const float4 w0 = *(const float4*)(Wr + (size_t)(d + q) * 8);
            const float4 w1 = *(const float4*)(Wr + (size_t)(d + q) * 8 + 4);
            acc[0] += xq[q] * w0.x; acc[1] += xq[q] * w0.y;
            acc[2] += xq[q] * w0.z; acc[3] += xq[q] * w0.w;
            acc[4] += xq[q] * w1.x; acc[5] += xq[q] * w1.y;
            acc[6] += xq[q] * w1.z; acc[7] += xq[q] * w1.w;
        }
    }
#pragma unroll
    for (int off = 16; off > 0; off >>= 1)
#pragma unroll
        for (int e = 0; e < NE; e++)
            acc[e] += __shfl_down_sync(0xffffffffu, acc[e], off);

    if (lane == 0) {
        float m = acc[0]; int ai = 0;
#pragma unroll
        for (int e = 1; e < NE; e++) if (acc[e] > m) { m = acc[e]; ai = e; }
        float p[NE], s = 0.f;
#pragma unroll
        for (int e = 0; e < NE; e++) { p[e] = expf(acc[e] - m); s += p[e]; }
        float inv = 1.f / s;
        g_gate[t]   = p[ai] * inv;
        g_expert[t] = ai;
#pragma unroll
        for (int e = 0; e < NE; e++) atomicAdd(&s_ps[e], p[e] * inv);
        atomicAdd(&s_cnt[ai], 1);
    }
    __syncthreads();
    if (tid < NE) {
        atomicAdd(&g_psum[tid], s_ps[tid]);
        atomicAdd(&g_cnt[tid],  s_cnt[tid]);
    }
}

// ---------------- bucketize ----------------
__global__ void bucketize_kernel() {
    int t = blockIdx.x * blockDim.x + threadIdx.x;
    if (t >= T_TOK) return;
    int e = g_expert[t];
    int lane = threadIdx.x & 31;
    unsigned mask = __match_any_sync(0xffffffffu, e);
    int leader = __ffs(mask) - 1;
    int rank   = __popc(mask & ((1u << lane) - 1));
    int base = 0;
    if (lane == leader) base = atomicAdd(&g_bcnt[e], __popc(mask));
    base = __shfl_sync(0xffffffffu, base, leader);
    int pos = base + rank;
    g_btok[e][pos]  = t;
    g_bgate[e][pos] = g_gate[t];
}

// ---------------- capacity selection: histogram + exact boundary ranking ----------------
// gate in (0.125, 1): key = float bits, bin = (key - 0x3E000000) >> 13 (monotone).
#define NBINS 3072
#define SEL_TPB 512
__device__ __forceinline__ int gate_bin(float g) {
    unsigned key = __float_as_uint(g);
    if (key < 0x3E000000u) return 0;
    unsigned rel = key - 0x3E000000u;
    int b = (int)(rel >> 13);
    return b < NBINS ? b : NBINS - 1;
}
__global__ __launch_bounds__(SEL_TPB) void select_kernel() {
    int e = blockIdx.x;
    int n = g_bcnt[e];
    int tid = threadIdx.x;

    if (n <= CAP) {   // everyone fits
        for (int i = tid; i < n; i += SEL_TPB) {
            g_stok[e][i]  = g_btok[e][i];
            g_sgate[e][i] = g_bgate[e][i];
        }
        if (tid == 0) g_scnt[e] = n;
        return;
    }

    __shared__ int hist[NBINS];
    __shared__ int sufx[NBINS];    // # tokens in strictly higher bins
    __shared__ int segoff[NBINS];
    __shared__ int tsum[SEL_TPB];

    for (int b = tid; b < NBINS; b += SEL_TPB) hist[b] = 0;
    __syncthreads();
    for (int i = tid; i < n; i += SEL_TPB)
        atomicAdd(&hist[gate_bin(g_bgate[e][i])], 1);
    __syncthreads();

    // suffix sums (each thread owns 6 bins)
    int local = 0;
#pragma unroll
    for (int j = 0; j < 6; j++) local += hist[tid * 6 + j];
    tsum[tid] = local;
    __syncthreads();
    for (int off = 1; off < SEL_TPB; off <<= 1) {
        int v = (tid + off < SEL_TPB) ? tsum[tid + off] : 0;
        __syncthreads();
        tsum[tid] += v;
        __syncthreads();
    }
    int run = tsum[tid] - local;   // sum over threads with index > tid
#pragma unroll
    for (int j = 5; j >= 0; j--) { int b = tid * 6 + j; sufx[b] = run; run += hist[b]; }
    __syncthreads();

    // counting-scatter into bin-sorted order
    for (int b = tid; b < NBINS; b += SEL_TPB) segoff[b] = n - sufx[b] - hist[b];
    __syncthreads();
    for (int i = tid; i < n; i += SEL_TPB) {
        float g = g_bgate[e][i]; int t = g_btok[e][i];
        int b = gate_bin(g);
        int p = atomicAdd(&segoff[b], 1);
        g_srt_tok[e][p]  = t;
        g_srt_gate[e][p] = g;
    }
    __syncthreads();

    // decide: global rank = sufx[b] + exact rank within own bin
    for (int i = tid; i < n; i += SEL_TPB) {
        float g = g_bgate[e][i]; int t = g_btok[e][i];
        int b = gate_bin(g);
        int hi = sufx[b];
        if (hi >= CAP) continue;
        int cnt = hist[b];
        bool sel;
        if (hi + cnt <= CAP) {
            sel = true;
        } else {
            int st = n - sufx[b] - cnt;
            int r = 0;
            for (int j = 0; j < cnt; j++) {
                float gj = g_srt_gate[e][st + j];
                if (gj > g || (gj == g && g_srt_tok[e][st + j] < t)) r++;
            }
            sel = (hi + r) < CAP;
        }
        if (sel) {
            int pos = atomicAdd(&g_scnt[e], 1);
            g_stok[e][pos]  = t;
            g_sgate[e][pos] = g;
        }
    }
}

// ---------------- 4-stage pipelined fp16 mma.sync GEMM (single sync/iter) ----------------
// MODE 0: H = relu(Xg @ W1 + b1)   (K=DM,  N=DFF)
// MODE 1: out = gate*(H @ W2 + b2) (K=DFF, N=DM)
template<int MODE>
__global__ void __launch_bounds__(256, 1) ffn_mma_kernel(const float* __restrict__ bias_all,
                                                         float* __restrict__ out)
{
    constexpr int KW  = MODE ? DFF : DM;
    constexpr int NW  = MODE ? DM  : DFF;
    constexpr int NKT = KW / BK;

    extern __shared__ char smem[];
    int e = blockIdx.z;
    int M = g_scnt[e];
    int m0 = blockIdx.y * BM;
    if (m0 >= M) return;
    int n0 = blockIdx.x * BN;

    int tid = threadIdx.x, wid = tid >> 5, lane = tid & 31;
    int gid = lane >> 2, tig = lane & 3;
    int quad = lane >> 3, lr = lane & 7;
    int m_base = (wid >> 2) * 64;   // 2 m-warps
    int n_base = (wid & 3) * 64;    // 4 n-warps

    uint32_t sbase = smem_u32(smem);
    const __half* Wbh = (MODE ? g_W2h : g_W1h) + (size_t)e * DM * DFF + n0;

    // ---- staging assignments ----
    const uint4* aptr[2]; uint32_t adst[2];
#pragma unroll
    for (int it = 0; it < 2; ++it) {
        int lin = tid + it * 256;
        int m = lin >> 2, q = lin & 3;
        int gm = m0 + m;
        int gmc = (gm < M) ? gm : 0;
        const __half* row = (MODE == 0)
            ? (g_Xh + (size_t)g_stok[e][gmc] * DM)
            : (g_H + ((size_t)e * CAP + gmc) * DFF);
        aptr[it] = (const uint4*)row + q;
        adst[it] = sbase + (uint32_t)(m * APITCH_H + q * 8) * 2;
    }
    const uint4* bptr[4]; uint32_t bdst[4];
#pragma unroll
    for (int it = 0; it < 4; ++it) {
        int lin = tid + it * 256;
        int k = lin >> 5, q = lin & 31;
        bptr[it] = (const uint4*)(Wbh + (size_t)k * NW) + q;
        bdst[it] = sbase + A_BYTES + (uint32_t)(k * BPITCH_H + q * 8) * 2;
    }

    // ---- ldmatrix base addresses ----
    uint32_t a_addr[4];
#pragma unroll
    for (int i = 0; i < 4; ++i) {
        int row = m_base + i * 16 + (quad & 1) * 8 + lr;
        int col = (quad >> 1) * 8;
        a_addr[i] = sbase + (uint32_t)(row * APITCH_H + col) * 2;
    }
    uint32_t b_addr[4];
#pragma unroll
    for (int jj = 0; jj < 4; ++jj) {
        int k = (quad & 1) * 8 + lr;
        int nn = n_base + (2 * jj + (quad >> 1)) * 8;
        b_addr[jj] = sbase + A_BYTES + (uint32_t)(k * BPITCH_H + nn) * 2;
    }

    float acc[4][8][4];
#pragma unroll
    for (int i = 0; i < 4; i++)
#pragma unroll
        for (int j = 0; j < 8; j++)
#pragma unroll
            for (int q = 0; q < 4; q++) acc[i][j][q] = 0.f;

    // ---- prologue: stages 0..NSTAGE-2 ----
#pragma unroll
    for (int s = 0; s < NSTAGE - 1; ++s) {
        uint32_t soff = (uint32_t)s * STAGE_BYTES;
#pragma unroll
        for (int it = 0; it < 2; ++it) cp16(adst[it] + soff, aptr[it] + (size_t)s * 4);
#pragma unroll
        for (int it = 0; it < 4; ++it) cp16(bdst[it] + soff, bptr[it] + (size_t)s * 4 * NW);
        cp_commit();
    }

    for (int kt = 0; kt < NKT; ++kt) {
        cp_wait<NSTAGE - 2>();       // stage kt landed
        __syncthreads();             // all warps done reading stage kt-1 (prefetch target)

        if (kt + NSTAGE - 1 < NKT) { // prefetch stage kt+3 into buf (kt-1)%4
            int s = (kt + NSTAGE - 1) % NSTAGE;
            uint32_t soff = (uint32_t)s * STAGE_BYTES;
            size_t ao = (size_t)(kt + NSTAGE - 1) * 4;
            size_t bo = (size_t)(kt + NSTAGE - 1) * 4 * NW;
#pragma unroll
            for (int it = 0; it < 2; ++it) cp16(adst[it] + soff, aptr[it] + ao);
#pragma unroll
            for (int it = 0; it < 4; ++it) cp16(bdst[it] + soff, bptr[it] + bo);
        }
        cp_commit();                 // uniform group accounting (may be empty)

        uint32_t soff = (uint32_t)(kt % NSTAGE) * STAGE_BYTES;
#pragma unroll
        for (int kk = 0; kk < 2; ++kk) {
            uint32_t akoff = soff + kk * 16 * 2;
            uint32_t bkoff = soff + kk * 16 * BPITCH_H * 2;
            unsigned A_[4][4];
#pragma unroll
            for (int i = 0; i < 4; ++i)
                ldsm_x4(A_[i][0], A_[i][1], A_[i][2], A_[i][3], a_addr[i] + akoff);
            unsigned B_[8][2];
#pragma unroll
            for (int jj = 0; jj < 4; ++jj)
                ldsm_x4_t(B_[2 * jj][0], B_[2 * jj][1], B_[2 * jj + 1][0], B_[2 * jj + 1][1],
                          b_addr[jj] + bkoff);
#pragma unroll
            for (int i = 0; i < 4; ++i)
#pragma unroll
                for (int j = 0; j < 8; ++j)
                    mma_f16(acc[i][j], A_[i], B_[j]);
        }
    }

    // ---- epilogue ----
    const float* biasp = bias_all + (size_t)e * NW + n0;
#pragma unroll
    for (int i = 0; i < 4; ++i) {
        int m_lo = m0 + m_base + i * 16 + gid;
        int m_hi = m_lo + 8;
        bool lo_ok = (m_lo < M), hi_ok = (m_hi < M);

        int tok_lo = 0, tok_hi = 0; float gt_lo = 0.f, gt_hi = 0.f;
        if (MODE == 1) {
            if (lo_ok) { tok_lo = g_stok[e][m_lo]; gt_lo = g_sgate[e][m_lo]; }
            if (hi_ok) { tok_hi = g_stok[e][m_hi]; gt_hi = g_sgate[e][m_hi]; }
        }
#pragma unroll
        for (int j = 0; j < 8; ++j) {
            int nc = n_base + j * 8 + tig * 2;
            float bv0 = biasp[nc], bv1 = biasp[nc + 1];
            if (MODE == 0) {
                if (lo_ok) {
                    __half2 o = __floats2half2_rn(fmaxf(acc[i][j][0] + bv0, 0.f),
                                                  fmaxf(acc[i][j][1] + bv1, 0.f));
                    *(__half2*)(g_H + ((size_t)e * CAP + m_lo) * DFF + n0 + nc) = o;
                }
                if (hi_ok) {
                    __half2 o = __floats2half2_rn(fmaxf(acc[i][j][2] + bv0, 0.f),
                                                  fmaxf(acc[i][j][3] + bv1, 0.f));
                    *(__half2*)(g_H + ((size_t)e * CAP + m_hi) * DFF + n0 + nc) = o;
                }
            } else {
                if (lo_ok) {
                    float2 o;
                    o.x = gt_lo * (acc[i][j][0] + bv0);
                    o.y = gt_lo * (acc[i][j][1] + bv1);
                    *(float2*)(out + (size_t)tok_lo * DM + n0 + nc) = o;
                }
                if (hi_ok) {
                    float2 o;
                    o.x = gt_hi * (acc[i][j][2] + bv0);
                    o.y = gt_hi * (acc[i][j][3] + bv1);
                    *(float2*)(out + (size_t)tok_hi * DM + n0 + nc) = o;
                }
            }
        }
    }
}

// ---------------- load-balancing loss ----------------
__global__ void loss_kernel(float* __restrict__ out, int out_size) {
    if (out_size > T_TOK * DM) {
        float loss = 0.f;
#pragma unroll
        for (int e = 0; e < NE; e++)
            loss += ((float)g_cnt[e] / (float)T_TOK) * (g_psum[e] / (float)T_TOK);
        out[T_TOK * DM] = (float)NE * loss;
    }
}

// ---------------- launch ----------------
extern "C" void kernel_launch(void* const* d_in, const int* in_sizes, int n_in,
                              void* d_out, int out_size) {
    const float* x   = (const float*)d_in[0];
    const float* Wr  = (const float*)d_in[1];
    const float* W1  = (const float*)d_in[2];
    const float* b1  = (const float*)d_in[3];
    const float* W2  = (const float*)d_in[4];
    const float* b2  = (const float*)d_in[5];
    float* out = (float*)d_out;

    cudaFuncSetAttribute(ffn_mma_kernel<0>, cudaFuncAttributeMaxDynamicSharedMemorySize, SMEM_BYTES);
    cudaFuncSetAttribute(ffn_mma_kernel<1>, cudaFuncAttributeMaxDynamicSharedMemorySize, SMEM_BYTES);

    void* w1h; cudaGetSymbolAddress(&w1h, g_W1h);
    void* w2h; cudaGetSymbolAddress(&w2h, g_W2h);

    cudaMemsetAsync(d_out, 0, (size_t)out_size * sizeof(float));
    init_kernel<<<1, 32>>>();

    const unsigned nthr = (unsigned)((size_t)NE * DM * DFF / 8);
    f2h_kernel<<<nthr / 256, 256>>>((const float4*)W1, (uint4*)w1h);
    f2h_kernel<<<nthr / 256, 256>>>((const float4*)W2, (uint4*)w2h);

    router_kernel<<<T_TOK / 8, 256>>>(x, Wr);
    bucketize_kernel<<<T_TOK / 256, 256>>>();
    select_kernel<<<NE, SEL_TPB>>>();

    ffn_mma_kernel<0><<<dim3(DFF / BN, CAP / BM, NE), 256, SMEM_BYTES>>>(b1, nullptr);
    ffn_mma_kernel<1><<<dim3(DM / BN, CAP / BM, NE), 256, SMEM_BYTES>>>(b2, out);

    loss_kernel<<<1, 1>>>(out, out_size);
}

// round 8
// speedup vs baseline: 7.3831x; 1.2216x over previous
#include <cuda_runtime.h>
#include <cuda_fp16.h>
#include <cstdint>

#define T_TOK 8192
#define DM    1024
#define NE    8
#define CAP   1024
#define DFF   4096

#define BM 128
#define BN 256
#define BK 32
#define NSTAGE 4
#define FFN_TPB 512

#define APITCH_H 40                      // halves per A smem row (32 data + 8 pad)
#define BPITCH_H 264                     // halves per B smem row (256 data + 8 pad)
#define A_BYTES (BM * APITCH_H * 2)      // 10240
#define B_BYTES (BK * BPITCH_H * 2)      // 16896
#define STAGE_BYTES (A_BYTES + B_BYTES)  // 27136
#define SMEM_BYTES (NSTAGE * STAGE_BYTES) // 108544

// ---------------- scratch ----------------
__device__ float  g_gate[T_TOK];
__device__ int    g_expert[T_TOK];
__device__ int    g_bcnt[NE];
__device__ int    g_btok[NE][T_TOK];
__device__ float  g_bgate[NE][T_TOK];
__device__ int    g_srt_tok[NE][T_TOK];
__device__ float  g_srt_gate[NE][T_TOK];
__device__ int    g_scnt[NE];
__device__ int    g_stok[NE][CAP];
__device__ float  g_sgate[NE][CAP];
__device__ float  g_psum[NE];
__device__ int    g_cnt[NE];
__device__ __half g_Xh[(size_t)T_TOK * DM];
__device__ __half g_W1h[(size_t)NE * DM * DFF];
__device__ __half g_W2h[(size_t)NE * DFF * DM];
__device__ __half g_H[(size_t)NE * CAP * DFF];

// ---------------- helpers ----------------
__device__ __forceinline__ uint32_t smem_u32(const void* p) {
    uint32_t a; asm("{ .reg .u64 t; cvta.to.shared.u64 t, %1; cvt.u32.u64 %0, t; }" : "=r"(a) : "l"(p));
    return a;
}
__device__ __forceinline__ void cp16(uint32_t dst, const void* src) {
    asm volatile("cp.async.cg.shared.global [%0], [%1], 16;" :: "r"(dst), "l"(src));
}
__device__ __forceinline__ void cp_commit() { asm volatile("cp.async.commit_group;"); }
template<int N> __device__ __forceinline__ void cp_wait() {
    asm volatile("cp.async.wait_group %0;" :: "n"(N));
}
__device__ __forceinline__ void ldsm_x4(unsigned& r0, unsigned& r1, unsigned& r2, unsigned& r3,
                                        uint32_t addr) {
    asm volatile("ldmatrix.sync.aligned.m8n8.x4.shared.b16 {%0,%1,%2,%3}, [%4];"
                 : "=r"(r0), "=r"(r1), "=r"(r2), "=r"(r3) : "r"(addr));
}
__device__ __forceinline__ void ldsm_x4_t(unsigned& r0, unsigned& r1, unsigned& r2, unsigned& r3,
                                          uint32_t addr) {
    asm volatile("ldmatrix.sync.aligned.m8n8.x4.trans.shared.b16 {%0,%1,%2,%3}, [%4];"
                 : "=r"(r0), "=r"(r1), "=r"(r2), "=r"(r3) : "r"(addr));
}
__device__ __forceinline__ void mma_f16(float* c, const unsigned* a, const unsigned* b) {
    asm volatile(
        "mma.sync.aligned.m16n8k16.row.col.f32.f16.f16.f32 "
        "{%0,%1,%2,%3},{%4,%5,%6,%7},{%8,%9},{%0,%1,%2,%3};"
        : "+f"(c[0]), "+f"(c[1]), "+f"(c[2]), "+f"(c[3])
        : "r"(a[0]), "r"(a[1]), "r"(a[2]), "r"(a[3]), "r"(b[0]), "r"(b[1]));
}

// ---------------- init ----------------
__global__ void init_kernel() {
    int i = threadIdx.x;
    if (i < NE) { g_bcnt[i] = 0; g_scnt[i] = 0; g_psum[i] = 0.f; g_cnt[i] = 0; }
}

// ---------------- fp32 -> fp16 weight convert ----------------
__global__ void f2h_kernel(const float4* __restrict__ src, uint4* __restrict__ dst) {
    size_t i = (size_t)blockIdx.x * blockDim.x + threadIdx.x;
    float4 v0 = src[2 * i], v1 = src[2 * i + 1];
    __half2 h0 = __floats2half2_rn(v0.x, v0.y);
    __half2 h1 = __floats2half2_rn(v0.z, v0.w);
    __half2 h2 = __floats2half2_rn(v1.x, v1.y);
    __half2 h3 = __floats2half2_rn(v1.z, v1.w);
    uint4 u;
    u.x = *reinterpret_cast<unsigned*>(&h0);
    u.y = *reinterpret_cast<unsigned*>(&h1);
    u.z = *reinterpret_cast<unsigned*>(&h2);
    u.w = *reinterpret_cast<unsigned*>(&h3);
    dst[i] = u;
}

// ---------------- router (round-6 layout: lane-strided rows, coalesced) ----------------
__global__ void router_kernel(const float* __restrict__ x, const float* __restrict__ Wr) {
    __shared__ float s_ps[NE];
    __shared__ int   s_cnt[NE];
    int tid = threadIdx.x;
    if (tid < NE) { s_ps[tid] = 0.f; s_cnt[tid] = 0; }
    __syncthreads();

    int warp = tid >> 5, lane = tid & 31;
    int t = blockIdx.x * 8 + warp;
    const float* xr = x + (size_t)t * DM;
    __half* xo = g_Xh + (size_t)t * DM;

    float acc[NE];
#pragma unroll
    for (int e = 0; e < NE; e++) acc[e] = 0.f;

#pragma unroll 8
    for (int k = 0; k < 32; k++) {
        int d = lane + 32 * k;
        float xv = xr[d];
        xo[d] = __float2half_rn(xv);
        float4 w0 = *(const float4*)(Wr + (size_t)d * 8);
        float4 w1 = *(const float4*)(Wr + (size_t)d * 8 + 4);
        acc[0] += xv * w0.x; acc[1] += xv * w0.y; acc[2] += xv * w0.z; acc[3] += xv * w0.w;
        acc[4] += xv * w1.x; acc[5] += xv * w1.y; acc[6] += xv * w1.z; acc[7] += xv * w1.w;
    }
#pragma unroll
    for (int off = 16; off > 0; off >>= 1)
#pragma unroll
        for (int e = 0; e < NE; e++)
            acc[e] += __shfl_down_sync(0xffffffffu, acc[e], off);

    if (lane == 0) {
        float m = acc[0]; int ai = 0;
#pragma unroll
        for (int e = 1; e < NE; e++) if (acc[e] > m) { m = acc[e]; ai = e; }
        float p[NE], s = 0.f;
#pragma unroll
        for (int e = 0; e < NE; e++) { p[e] = expf(acc[e] - m); s += p[e]; }
        float inv = 1.f / s;
        g_gate[t]   = p[ai] * inv;
        g_expert[t] = ai;
#pragma unroll
        for (int e = 0; e < NE; e++) atomicAdd(&s_ps[e], p[e] * inv);
        atomicAdd(&s_cnt[ai], 1);
    }
    __syncthreads();
    if (tid < NE) {
        atomicAdd(&g_psum[tid], s_ps[tid]);
        atomicAdd(&g_cnt[tid],  s_cnt[tid]);
    }
}

// ---------------- bucketize ----------------
__global__ void bucketize_kernel() {
    int t = blockIdx.x * blockDim.x + threadIdx.x;
    if (t >= T_TOK) return;
    int e = g_expert[t];
    int lane = threadIdx.x & 31;
    unsigned mask = __match_any_sync(0xffffffffu, e);
    int leader = __ffs(mask) - 1;
    int rank   = __popc(mask & ((1u << lane) - 1));
    int base = 0;
    if (lane == leader) base = atomicAdd(&g_bcnt[e], __popc(mask));
    base = __shfl_sync(0xffffffffu, base, leader);
    int pos = base + rank;
    g_btok[e][pos]  = t;
    g_bgate[e][pos] = g_gate[t];
}

// ---------------- capacity selection: histogram + exact boundary ranking ----------------
#define NBINS 3072
#define SEL_TPB 512
__device__ __forceinline__ int gate_bin(float g) {
    unsigned key = __float_as_uint(g);
    if (key < 0x3E000000u) return 0;
    unsigned rel = key - 0x3E000000u;
    int b = (int)(rel >> 13);
    return b < NBINS ? b : NBINS - 1;
}
__global__ __launch_bounds__(SEL_TPB) void select_kernel() {
    int e = blockIdx.x;
    int n = g_bcnt[e];
    int tid = threadIdx.x;

    if (n <= CAP) {
        for (int i = tid; i < n; i += SEL_TPB) {
            g_stok[e][i]  = g_btok[e][i];
            g_sgate[e][i] = g_bgate[e][i];
        }
        if (tid == 0) g_scnt[e] = n;
        return;
    }

    __shared__ int hist[NBINS];
    __shared__ int sufx[NBINS];
    __shared__ int segoff[NBINS];
    __shared__ int tsum[SEL_TPB];

    for (int b = tid; b < NBINS; b += SEL_TPB) hist[b] = 0;
    __syncthreads();
    for (int i = tid; i < n; i += SEL_TPB)
        atomicAdd(&hist[gate_bin(g_bgate[e][i])], 1);
    __syncthreads();

    int local = 0;
#pragma unroll
    for (int j = 0; j < 6; j++) local += hist[tid * 6 + j];
    tsum[tid] = local;
    __syncthreads();
    for (int off = 1; off < SEL_TPB; off <<= 1) {
        int v = (tid + off < SEL_TPB) ? tsum[tid + off] : 0;
        __syncthreads();
        tsum[tid] += v;
        __syncthreads();
    }
    int run = tsum[tid] - local;
#pragma unroll
    for (int j = 5; j >= 0; j--) { int b = tid * 6 + j; sufx[b] = run; run += hist[b]; }
    __syncthreads();

    for (int b = tid; b < NBINS; b += SEL_TPB) segoff[b] = n - sufx[b] - hist[b];
    __syncthreads();
    for (int i = tid; i < n; i += SEL_TPB) {
        float g = g_bgate[e][i]; int t = g_btok[e][i];
        int b = gate_bin(g);
        int p = atomicAdd(&segoff[b], 1);
        g_srt_tok[e][p]  = t;
        g_srt_gate[e][p] = g;
    }
    __syncthreads();

    for (int i = tid; i < n; i += SEL_TPB) {
        float g = g_bgate[e][i]; int t = g_btok[e][i];
        int b = gate_bin(g);
        int hi = sufx[b];
        if (hi >= CAP) continue;
        int cnt = hist[b];
        bool sel;
        if (hi + cnt <= CAP) {
            sel = true;
        } else {
            int st = n - sufx[b] - cnt;
            int r = 0;
            for (int j = 0; j < cnt; j++) {
                float gj = g_srt_gate[e][st + j];
                if (gj > g || (gj == g && g_srt_tok[e][st + j] < t)) r++;
            }
            sel = (hi + r) < CAP;
        }
        if (sel) {
            int pos = atomicAdd(&g_scnt[e], 1);
            g_stok[e][pos]  = t;
            g_sgate[e][pos] = g;
        }
    }
}

// ---------------- 4-stage pipelined fp16 mma.sync GEMM, 512 threads / 16 warps ----------------
// MODE 0: H = relu(Xg @ W1 + b1)   (K=DM,  N=DFF)
// MODE 1: out = gate*(H @ W2 + b2) (K=DFF, N=DM)
// CTA 128x256, BK=32, 16 warps (4m x 4n), warp tile 32x64.
template<int MODE>
__global__ void __launch_bounds__(FFN_TPB, 1) ffn_mma_kernel(const float* __restrict__ bias_all,
                                                             float* __restrict__ out)
{
    constexpr int KW  = MODE ? DFF : DM;
    constexpr int NW  = MODE ? DM  : DFF;
    constexpr int NKT = KW / BK;

    extern __shared__ char smem[];
    int e = blockIdx.z;
    int M = g_scnt[e];
    int m0 = blockIdx.y * BM;
    if (m0 >= M) return;
    int n0 = blockIdx.x * BN;

    int tid = threadIdx.x, wid = tid >> 5, lane = tid & 31;
    int gid = lane >> 2, tig = lane & 3;
    int quad = lane >> 3, lr = lane & 7;
    int m_base = (wid >> 2) * 32;   // 4 m-warps
    int n_base = (wid & 3) * 64;    // 4 n-warps

    uint32_t sbase = smem_u32(smem);
    const __half* Wbh = (MODE ? g_W2h : g_W1h) + (size_t)e * DM * DFF + n0;

    // ---- staging: A 512 chunks (1/thread), B 1024 chunks (2/thread) ----
    const uint4* aptr; uint32_t adst;
    {
        int m = tid >> 2, q = tid & 3;
        int gm = m0 + m;
        int gmc = (gm < M) ? gm : 0;
        const __half* row = (MODE == 0)
            ? (g_Xh + (size_t)g_stok[e][gmc] * DM)
            : (g_H + ((size_t)e * CAP + gmc) * DFF);
        aptr = (const uint4*)row + q;
        adst = sbase + (uint32_t)(m * APITCH_H + q * 8) * 2;
    }
    const uint4* bptr[2]; uint32_t bdst[2];
#pragma unroll
    for (int it = 0; it < 2; ++it) {
        int lin = tid + it * FFN_TPB;
        int k = lin >> 5, q = lin & 31;
        bptr[it] = (const uint4*)(Wbh + (size_t)k * NW) + q;
        bdst[it] = sbase + A_BYTES + (uint32_t)(k * BPITCH_H + q * 8) * 2;
    }

    // ---- ldmatrix base addresses ----
    uint32_t a_addr[2];
#pragma unroll
    for (int i = 0; i < 2; ++i) {
        int row = m_base + i * 16 + (quad & 1) * 8 + lr;
        int col = (quad >> 1) * 8;
        a_addr[i] = sbase + (uint32_t)(row * APITCH_H + col) * 2;
    }
    uint32_t b_addr[4];
#pragma unroll
    for (int jj = 0; jj < 4; ++jj) {
        int k = (quad & 1) * 8 + lr;
        int nn = n_base + (2 * jj + (quad >> 1)) * 8;
        b_addr[jj] = sbase + A_BYTES + (uint32_t)(k * BPITCH_H + nn) * 2;
    }

    float acc[2][8][4];
#pragma unroll
    for (int i = 0; i < 2; i++)
#pragma unroll
        for (int j = 0; j < 8; j++)
#pragma unroll
            for (int q = 0; q < 4; q++) acc[i][j][q] = 0.f;

    // ---- prologue: stages 0..NSTAGE-2 ----
#pragma unroll
    for (int s = 0; s < NSTAGE - 1; ++s) {
        uint32_t soff = (uint32_t)s * STAGE_BYTES;
        cp16(adst + soff, aptr + (size_t)s * 4);
#pragma unroll
        for (int it = 0; it < 2; ++it) cp16(bdst[it] + soff, bptr[it] + (size_t)s * 4 * NW);
        cp_commit();
    }

    for (int kt = 0; kt < NKT; ++kt) {
        cp_wait<NSTAGE - 2>();
        __syncthreads();

        if (kt + NSTAGE - 1 < NKT) {
            int s = (kt + NSTAGE - 1) % NSTAGE;
            uint32_t soff = (uint32_t)s * STAGE_BYTES;
            size_t ao = (size_t)(kt + NSTAGE - 1) * 4;
            size_t bo = (size_t)(kt + NSTAGE - 1) * 4 * NW;
            cp16(adst + soff, aptr + ao);
#pragma unroll
            for (int it = 0; it < 2; ++it) cp16(bdst[it] + soff, bptr[it] + bo);
        }
        cp_commit();

        uint32_t soff = (uint32_t)(kt % NSTAGE) * STAGE_BYTES;
#pragma unroll
        for (int kk = 0; kk < 2; ++kk) {
            uint32_t akoff = soff + kk * 16 * 2;
            uint32_t bkoff = soff + kk * 16 * BPITCH_H * 2;
            unsigned A_[2][4];
#pragma unroll
            for (int i = 0; i < 2; ++i)
                ldsm_x4(A_[i][0], A_[i][1], A_[i][2], A_[i][3], a_addr[i] + akoff);
            unsigned B_[8][2];
#pragma unroll
            for (int jj = 0; jj < 4; ++jj)
                ldsm_x4_t(B_[2 * jj][0], B_[2 * jj][1], B_[2 * jj + 1][0], B_[2 * jj + 1][1],
                          b_addr[jj] + bkoff);
#pragma unroll
            for (int i = 0; i < 2; ++i)
#pragma unroll
                for (int j = 0; j < 8; ++j)
                    mma_f16(acc[i][j], A_[i], B_[j]);
        }
    }

    // ---- epilogue ----
    const float* biasp = bias_all + (size_t)e * NW + n0;
#pragma unroll
    for (int i = 0; i < 2; ++i) {
        int m_lo = m0 + m_base + i * 16 + gid;
        int m_hi = m_lo + 8;
        bool lo_ok = (m_lo < M), hi_ok = (m_hi < M);

        int tok_lo = 0, tok_hi = 0; float gt_lo = 0.f, gt_hi = 0.f;
        if (MODE == 1) {
            if (lo_ok) { tok_lo = g_stok[e][m_lo]; gt_lo = g_sgate[e][m_lo]; }
            if (hi_ok) { tok_hi = g_stok[e][m_hi]; gt_hi = g_sgate[e][m_hi]; }
        }
#pragma unroll
        for (int j = 0; j < 8; ++j) {
            int nc = n_base + j * 8 + tig * 2;
            float bv0 = biasp[nc], bv1 = biasp[nc + 1];
            if (MODE == 0) {
                if (lo_ok) {
                    __half2 o = __floats2half2_rn(fmaxf(acc[i][j][0] + bv0, 0.f),
                                                  fmaxf(acc[i][j][1] + bv1, 0.f));
                    *(__half2*)(g_H + ((size_t)e * CAP + m_lo) * DFF + n0 + nc) = o;
                }
                if (hi_ok) {
                    __half2 o = __floats2half2_rn(fmaxf(acc[i][j][2] + bv0, 0.f),
                                                  fmaxf(acc[i][j][3] + bv1, 0.f));
                    *(__half2*)(g_H + ((size_t)e * CAP + m_hi) * DFF + n0 + nc) = o;
                }
            } else {
                if (lo_ok) {
                    float2 o;
                    o.x = gt_lo * (acc[i][j][0] + bv0);
                    o.y = gt_lo * (acc[i][j][1] + bv1);
                    *(float2*)(out + (size_t)tok_lo * DM + n0 + nc) = o;
                }
                if (hi_ok) {
                    float2 o;
                    o.x = gt_hi * (acc[i][j][2] + bv0);
                    o.y = gt_hi * (acc[i][j][3] + bv1);
                    *(float2*)(out + (size_t)tok_hi * DM + n0 + nc) = o;
                }
            }
        }
    }
}

// ---------------- load-balancing loss ----------------
__global__ void loss_kernel(float* __restrict__ out, int out_size) {
    if (out_size > T_TOK * DM) {
        float loss = 0.f;
#pragma unroll
        for (int e = 0; e < NE; e++)
            loss += ((float)g_cnt[e] / (float)T_TOK) * (g_psum[e] / (float)T_TOK);
        out[T_TOK * DM] = (float)NE * loss;
    }
}

// ---------------- launch ----------------
extern "C" void kernel_launch(void* const* d_in, const int* in_sizes, int n_in,
                              void* d_out, int out_size) {
    const float* x   = (const float*)d_in[0];
    const float* Wr  = (const float*)d_in[1];
    const float* W1  = (const float*)d_in[2];
    const float* b1  = (const float*)d_in[3];
    const float* W2  = (const float*)d_in[4];
    const float* b2  = (const float*)d_in[5];
    float* out = (float*)d_out;

    cudaFuncSetAttribute(ffn_mma_kernel<0>, cudaFuncAttributeMaxDynamicSharedMemorySize, SMEM_BYTES);
    cudaFuncSetAttribute(ffn_mma_kernel<1>, cudaFuncAttributeMaxDynamicSharedMemorySize, SMEM_BYTES);

    void* w1h; cudaGetSymbolAddress(&w1h, g_W1h);
    void* w2h; cudaGetSymbolAddress(&w2h, g_W2h);

    cudaMemsetAsync(d_out, 0, (size_t)out_size * sizeof(float));
    init_kernel<<<1, 32>>>();

    const unsigned nthr = (unsigned)((size_t)NE * DM * DFF / 8);
    f2h_kernel<<<nthr / 256, 256>>>((const float4*)W1, (uint4*)w1h);
    f2h_kernel<<<nthr / 256, 256>>>((const float4*)W2, (uint4*)w2h);

    router_kernel<<<T_TOK / 8, 256>>>(x, Wr);
    bucketize_kernel<<<T_TOK / 256, 256>>>();
    select_kernel<<<NE, SEL_TPB>>>();

    ffn_mma_kernel<0><<<dim3(DFF / BN, CAP / BM, NE), FFN_TPB, SMEM_BYTES>>>(b1, nullptr);
    ffn_mma_kernel<1><<<dim3(DM / BN, CAP / BM, NE), FFN_TPB, SMEM_BYTES>>>(b2, out);

    loss_kernel<<<1, 1>>>(out, out_size);
}